// round 1
// baseline (speedup 1.0000x reference)
#include <cuda_runtime.h>
#include <math.h>

#define BB 8
#define TT 1024
#define CC 768
#define HH 12
#define DD 64
#define BH (BB*HH)          // 96
#define SCALE 0.125f        // 64^-0.5

// ---------------- scratch (device globals; no allocation allowed) ----------------
__device__ float g_q[BB*TT*CC];                 // (B,T,C) layout; head h at col h*64
__device__ float g_k[BB*TT*CC];
__device__ float g_v[BB*TT*CC];
__device__ float g_ctx[BB*TT*CC];               // attention output pre-projection
__device__ float g_att[(size_t)BH*TT*TT];       // 96*1024*1024 floats (~402 MB)
__device__ float g_relh[BH*TT*32];              // (bh, q, kh)
__device__ float g_relw[BH*TT*32];              // (bh, q, kw)

// =================================================================================
// Kernel A: fused QKV projections. 128x128x16 tiled fp32 GEMM, 8x8 per thread.
// grid (N/128=6, M/128=64, 3), block 256.
// =================================================================================
__global__ void __launch_bounds__(256) qkv_gemm(const float* __restrict__ x,
                                                const float* __restrict__ ctxin,
                                                const float* __restrict__ Wq,
                                                const float* __restrict__ Wk,
                                                const float* __restrict__ Wv)
{
    const int which = blockIdx.z;
    const float* A = (which == 0) ? x : ctxin;
    const float* W = (which == 0) ? Wq : (which == 1 ? Wk : Wv);
    float* Out = (which == 0) ? g_q : (which == 1 ? g_k : g_v);

    const int n0 = blockIdx.x * 128;
    const int m0 = blockIdx.y * 128;
    const int tid = threadIdx.x;

    __shared__ float As[16][128];
    __shared__ float Bs[16][128];

    float acc[8][8];
#pragma unroll
    for (int i = 0; i < 8; i++)
#pragma unroll
        for (int j = 0; j < 8; j++) acc[i][j] = 0.0f;

    const int tm = (tid >> 4) * 8;
    const int tn = (tid & 15) * 8;

    for (int k0 = 0; k0 < CC; k0 += 16) {
        // load A tile 128x16 (row-major, ld=768), store transposed As[k][m]
#pragma unroll
        for (int i = 0; i < 2; i++) {
            int q = tid * 2 + i;          // 0..511 quads
            int row = q >> 2;             // 0..127
            int cq  = q & 3;              // 0..3
            float4 v = *(const float4*)(&A[(size_t)(m0 + row) * CC + k0 + cq * 4]);
            As[cq*4+0][row] = v.x;
            As[cq*4+1][row] = v.y;
            As[cq*4+2][row] = v.z;
            As[cq*4+3][row] = v.w;
        }
        // load B tile 16x128 (W row-major 768x768)
#pragma unroll
        for (int i = 0; i < 2; i++) {
            int q = tid * 2 + i;
            int row = q >> 5;             // 0..15
            int cq  = q & 31;             // 0..31
            *(float4*)(&Bs[row][cq*4]) =
                *(const float4*)(&W[(size_t)(k0 + row) * 768 + n0 + cq * 4]);
        }
        __syncthreads();
#pragma unroll
        for (int kk = 0; kk < 16; kk++) {
            float4 a0 = *(const float4*)(&As[kk][tm]);
            float4 a1 = *(const float4*)(&As[kk][tm + 4]);
            float4 b0 = *(const float4*)(&Bs[kk][tn]);
            float4 b1 = *(const float4*)(&Bs[kk][tn + 4]);
            float a[8] = {a0.x,a0.y,a0.z,a0.w,a1.x,a1.y,a1.z,a1.w};
            float b[8] = {b0.x,b0.y,b0.z,b0.w,b1.x,b1.y,b1.z,b1.w};
#pragma unroll
            for (int i = 0; i < 8; i++)
#pragma unroll
                for (int j = 0; j < 8; j++) acc[i][j] = fmaf(a[i], b[j], acc[i][j]);
        }
        __syncthreads();
    }

#pragma unroll
    for (int i = 0; i < 8; i++) {
        float4 v0 = make_float4(acc[i][0],acc[i][1],acc[i][2],acc[i][3]);
        float4 v1 = make_float4(acc[i][4],acc[i][5],acc[i][6],acc[i][7]);
        *(float4*)(&Out[(size_t)(m0 + tm + i) * 768 + n0 + tn])     = v0;
        *(float4*)(&Out[(size_t)(m0 + tm + i) * 768 + n0 + tn + 4]) = v1;
    }
}

// =================================================================================
// Kernel B: decomposed rel-pos bias tables.
//   relh[bh,q,kh] = dot(q_vec, rel_pos_h[i-kh+31]),  i=q>>5
//   relw[bh,q,kw] = dot(q_vec, rel_pos_w[j-kw+31]),  j=q&31
// grid BH*T blocks, 64 threads.
// =================================================================================
__global__ void __launch_bounds__(64) relbias_kernel(const float* __restrict__ rph,
                                                     const float* __restrict__ rpw)
{
    const int bq = blockIdx.x;        // bh*1024 + q
    const int bh = bq >> 10;
    const int q  = bq & 1023;
    const int b = bh / HH, h = bh % HH;
    const int i = q >> 5, j = q & 31;
    const int t = threadIdx.x;

    __shared__ float qs[64];
    qs[t] = g_q[(size_t)(b * TT + q) * CC + h * DD + t];
    __syncthreads();

    if (t < 32) {
        const float* tab = rph + (size_t)(i - t + 31) * DD;
        float acc = 0.0f;
#pragma unroll
        for (int c = 0; c < DD; c++) acc = fmaf(qs[c], tab[c], acc);
        g_relh[(size_t)bq * 32 + t] = acc;
    } else {
        const int kw = t - 32;
        const float* tab = rpw + (size_t)(j - kw + 31) * DD;
        float acc = 0.0f;
#pragma unroll
        for (int c = 0; c < DD; c++) acc = fmaf(qs[c], tab[c], acc);
        g_relw[(size_t)bq * 32 + kw] = acc;
    }
}

// =================================================================================
// Kernel C: scores = Q K^T * SCALE + bias  -> g_att.  Per batch z=bh: 1024x1024x64.
// grid (8, 8, 96), block 256.
// =================================================================================
__global__ void __launch_bounds__(256) scores_gemm()
{
    const int z = blockIdx.z;
    const int b = z / HH, h = z % HH;
    const int n0 = blockIdx.x * 128;
    const int m0 = blockIdx.y * 128;
    const int tid = threadIdx.x;

    const float* qb = g_q + (size_t)b * TT * CC + h * DD;
    const float* kb = g_k + (size_t)b * TT * CC + h * DD;

    __shared__ float As[16][128];
    __shared__ float Bs[16][128];

    float acc[8][8];
#pragma unroll
    for (int i = 0; i < 8; i++)
#pragma unroll
        for (int j = 0; j < 8; j++) acc[i][j] = 0.0f;

    const int tm = (tid >> 4) * 8;
    const int tn = (tid & 15) * 8;

    for (int k0 = 0; k0 < DD; k0 += 16) {
        // A tile: q rows, contiguous in c (ld 768)
#pragma unroll
        for (int i = 0; i < 2; i++) {
            int q = tid * 2 + i;
            int row = q >> 2;
            int cq  = q & 3;
            float4 v = *(const float4*)(&qb[(size_t)(m0 + row) * CC + k0 + cq * 4]);
            As[cq*4+0][row] = v.x;
            As[cq*4+1][row] = v.y;
            As[cq*4+2][row] = v.z;
            As[cq*4+3][row] = v.w;
        }
        // B tile: k rows (n index), contiguous in c -> transpose into Bs[c][n]
#pragma unroll
        for (int i = 0; i < 2; i++) {
            int q = tid * 2 + i;
            int n  = q >> 2;
            int cq = q & 3;
            float4 v = *(const float4*)(&kb[(size_t)(n0 + n) * CC + k0 + cq * 4]);
            Bs[cq*4+0][n] = v.x;
            Bs[cq*4+1][n] = v.y;
            Bs[cq*4+2][n] = v.z;
            Bs[cq*4+3][n] = v.w;
        }
        __syncthreads();
#pragma unroll
        for (int kk = 0; kk < 16; kk++) {
            float4 a0 = *(const float4*)(&As[kk][tm]);
            float4 a1 = *(const float4*)(&As[kk][tm + 4]);
            float4 b0 = *(const float4*)(&Bs[kk][tn]);
            float4 b1 = *(const float4*)(&Bs[kk][tn + 4]);
            float a[8] = {a0.x,a0.y,a0.z,a0.w,a1.x,a1.y,a1.z,a1.w};
            float bb[8] = {b0.x,b0.y,b0.z,b0.w,b1.x,b1.y,b1.z,b1.w};
#pragma unroll
            for (int i = 0; i < 8; i++)
#pragma unroll
                for (int j = 0; j < 8; j++) acc[i][j] = fmaf(a[i], bb[j], acc[i][j]);
        }
        __syncthreads();
    }

#pragma unroll
    for (int i = 0; i < 8; i++) {
        const int m = m0 + tm + i;
        const size_t rbase = ((size_t)z * TT + m) * 32;
        const float bh_bias = g_relh[rbase + ((n0 + tn) >> 5)]; // 8-wide tn block stays in one kh group
        float* outp = &g_att[((size_t)z * TT + m) * TT + n0 + tn];
#pragma unroll
        for (int j = 0; j < 8; j++) {
            const int n = n0 + tn + j;
            outp[j] = acc[i][j] * SCALE + bh_bias + g_relw[rbase + (n & 31)];
        }
    }
}

// =================================================================================
// Kernel D: row softmax over T=1024, in place. grid BH*T, block 256 (float4/thread).
// =================================================================================
__global__ void __launch_bounds__(256) softmax_rows()
{
    const size_t row = blockIdx.x;
    float* p = g_att + row * TT;
    const int tid = threadIdx.x;

    float4 v = ((float4*)p)[tid];
    float m = fmaxf(fmaxf(v.x, v.y), fmaxf(v.z, v.w));
#pragma unroll
    for (int o = 16; o; o >>= 1) m = fmaxf(m, __shfl_xor_sync(0xffffffffu, m, o));

    __shared__ float red[8];
    if ((tid & 31) == 0) red[tid >> 5] = m;
    __syncthreads();
    float bm = red[0];
#pragma unroll
    for (int i = 1; i < 8; i++) bm = fmaxf(bm, red[i]);

    v.x = __expf(v.x - bm);
    v.y = __expf(v.y - bm);
    v.z = __expf(v.z - bm);
    v.w = __expf(v.w - bm);
    float s = v.x + v.y + v.z + v.w;
#pragma unroll
    for (int o = 16; o; o >>= 1) s += __shfl_xor_sync(0xffffffffu, s, o);
    __syncthreads();                 // red[] reuse
    if ((tid & 31) == 0) red[tid >> 5] = s;
    __syncthreads();
    float bs = 0.0f;
#pragma unroll
    for (int i = 0; i < 8; i++) bs += red[i];
    const float inv = 1.0f / bs;

    v.x *= inv; v.y *= inv; v.z *= inv; v.w *= inv;
    ((float4*)p)[tid] = v;
}

// =================================================================================
// Kernel E: ctx = P @ V per bh. 1024x64x1024, tiles 64x64x32, 4x4 per thread.
// grid (16, 96), block 256.
// =================================================================================
__global__ void __launch_bounds__(256) pv_gemm()
{
    const int z = blockIdx.y;
    const int b = z / HH, h = z % HH;
    const int m0 = blockIdx.x * 64;
    const int tid = threadIdx.x;

    const float* pr = g_att + (size_t)z * TT * TT;
    const float* vb = g_v + (size_t)b * TT * CC + h * DD;

    __shared__ float As[32][64];
    __shared__ float Bs[32][64];

    float acc[4][4];
#pragma unroll
    for (int i = 0; i < 4; i++)
#pragma unroll
        for (int j = 0; j < 4; j++) acc[i][j] = 0.0f;

    const int tm = (tid >> 4) * 4;
    const int tn = (tid & 15) * 4;

    for (int k0 = 0; k0 < TT; k0 += 32) {
        // A: probs tile 64 rows x 32 k (ld 1024), transpose into As[k][m]
#pragma unroll
        for (int i = 0; i < 2; i++) {
            int q = tid * 2 + i;          // 0..511
            int row = q >> 3;             // 0..63
            int cq  = q & 7;              // 0..7
            float4 v = *(const float4*)(&pr[(size_t)(m0 + row) * TT + k0 + cq * 4]);
            As[cq*4+0][row] = v.x;
            As[cq*4+1][row] = v.y;
            As[cq*4+2][row] = v.z;
            As[cq*4+3][row] = v.w;
        }
        // B: v tile 32 k-rows x 64 d (ld 768)
#pragma unroll
        for (int i = 0; i < 2; i++) {
            int q = tid * 2 + i;
            int row = q >> 4;             // 0..31
            int cq  = q & 15;             // 0..15
            *(float4*)(&Bs[row][cq*4]) =
                *(const float4*)(&vb[(size_t)(k0 + row) * CC + cq * 4]);
        }
        __syncthreads();
#pragma unroll
        for (int kk = 0; kk < 32; kk++) {
            float4 a4 = *(const float4*)(&As[kk][tm]);
            float4 b4 = *(const float4*)(&Bs[kk][tn]);
            float a[4] = {a4.x,a4.y,a4.z,a4.w};
            float bb[4] = {b4.x,b4.y,b4.z,b4.w};
#pragma unroll
            for (int i = 0; i < 4; i++)
#pragma unroll
                for (int j = 0; j < 4; j++) acc[i][j] = fmaf(a[i], bb[j], acc[i][j]);
        }
        __syncthreads();
    }

#pragma unroll
    for (int i = 0; i < 4; i++) {
        float4 v0 = make_float4(acc[i][0],acc[i][1],acc[i][2],acc[i][3]);
        *(float4*)(&g_ctx[(size_t)(b * TT + m0 + tm + i) * CC + h * DD + tn]) = v0;
    }
}

// =================================================================================
// Kernel F: out = ctx @ Wo + bo. Same shape as kernel A. grid (6, 64), block 256.
// =================================================================================
__global__ void __launch_bounds__(256) out_gemm(const float* __restrict__ Wo,
                                                const float* __restrict__ bo,
                                                float* __restrict__ out)
{
    const int n0 = blockIdx.x * 128;
    const int m0 = blockIdx.y * 128;
    const int tid = threadIdx.x;

    __shared__ float As[16][128];
    __shared__ float Bs[16][128];

    float acc[8][8];
#pragma unroll
    for (int i = 0; i < 8; i++)
#pragma unroll
        for (int j = 0; j < 8; j++) acc[i][j] = 0.0f;

    const int tm = (tid >> 4) * 8;
    const int tn = (tid & 15) * 8;

    for (int k0 = 0; k0 < 768; k0 += 16) {
#pragma unroll
        for (int i = 0; i < 2; i++) {
            int q = tid * 2 + i;
            int row = q >> 2;
            int cq  = q & 3;
            float4 v = *(const float4*)(&g_ctx[(size_t)(m0 + row) * CC + k0 + cq * 4]);
            As[cq*4+0][row] = v.x;
            As[cq*4+1][row] = v.y;
            As[cq*4+2][row] = v.z;
            As[cq*4+3][row] = v.w;
        }
#pragma unroll
        for (int i = 0; i < 2; i++) {
            int q = tid * 2 + i;
            int row = q >> 5;
            int cq  = q & 31;
            *(float4*)(&Bs[row][cq*4]) =
                *(const float4*)(&Wo[(size_t)(k0 + row) * CC + n0 + cq * 4]);
        }
        __syncthreads();
#pragma unroll
        for (int kk = 0; kk < 16; kk++) {
            float4 a0 = *(const float4*)(&As[kk][tm]);
            float4 a1 = *(const float4*)(&As[kk][tm + 4]);
            float4 b0 = *(const float4*)(&Bs[kk][tn]);
            float4 b1 = *(const float4*)(&Bs[kk][tn + 4]);
            float a[8] = {a0.x,a0.y,a0.z,a0.w,a1.x,a1.y,a1.z,a1.w};
            float bb[8] = {b0.x,b0.y,b0.z,b0.w,b1.x,b1.y,b1.z,b1.w};
#pragma unroll
            for (int i = 0; i < 8; i++)
#pragma unroll
                for (int j = 0; j < 8; j++) acc[i][j] = fmaf(a[i], bb[j], acc[i][j]);
        }
        __syncthreads();
    }

#pragma unroll
    for (int i = 0; i < 8; i++) {
        float4 v0, v1;
        v0.x = acc[i][0] + bo[n0+tn+0]; v0.y = acc[i][1] + bo[n0+tn+1];
        v0.z = acc[i][2] + bo[n0+tn+2]; v0.w = acc[i][3] + bo[n0+tn+3];
        v1.x = acc[i][4] + bo[n0+tn+4]; v1.y = acc[i][5] + bo[n0+tn+5];
        v1.z = acc[i][6] + bo[n0+tn+6]; v1.w = acc[i][7] + bo[n0+tn+7];
        *(float4*)(&out[(size_t)(m0 + tm + i) * CC + n0 + tn])     = v0;
        *(float4*)(&out[(size_t)(m0 + tm + i) * CC + n0 + tn + 4]) = v1;
    }
}

// =================================================================================
extern "C" void kernel_launch(void* const* d_in, const int* in_sizes, int n_in,
                              void* d_out, int out_size)
{
    const float* x   = (const float*)d_in[0];
    const float* ctx = (const float*)d_in[1];
    const float* Wq  = (const float*)d_in[2];
    const float* Wk  = (const float*)d_in[3];
    const float* Wv  = (const float*)d_in[4];
    const float* Wo  = (const float*)d_in[5];
    const float* bo  = (const float*)d_in[6];
    const float* rph = (const float*)d_in[7];
    const float* rpw = (const float*)d_in[8];
    float* out = (float*)d_out;

    qkv_gemm<<<dim3(6, 64, 3), 256>>>(x, ctx, Wq, Wk, Wv);
    relbias_kernel<<<BH * TT, 64>>>(rph, rpw);
    scores_gemm<<<dim3(8, 8, 96), 256>>>();
    softmax_rows<<<BH * TT, 256>>>();
    pv_gemm<<<dim3(16, 96), 256>>>();
    out_gemm<<<dim3(6, 64), 256>>>(Wo, bo, out);
}

// round 2
// speedup vs baseline: 1.1317x; 1.1317x over previous
#include <cuda_runtime.h>
#include <math.h>

#define BB 8
#define TT 1024
#define CC 768
#define HH 12
#define DD 64
#define BH (BB*HH)          // 96
#define SCALE 0.125f        // 64^-0.5

// ---------------- scratch (device globals; no allocation allowed) ----------------
__device__ float g_q[BB*TT*CC];                 // (B,T,C) layout; head h at col h*64
__device__ float g_k[BB*TT*CC];
__device__ float g_v[BB*TT*CC];
__device__ float g_ctx[BB*TT*CC];               // attention output pre-projection
__device__ float g_relh[BH*TT*32];              // (bh, q, kh)
__device__ float g_relw[BH*TT*32];              // (bh, q, kw)

// ---------------- packed fp32x2 helpers (FFMA2: PTX-only on sm_103a) -------------
typedef unsigned long long ull;

__device__ __forceinline__ ull bc2(float v) {               // broadcast {v,v}
    ull r; asm("mov.b64 %0, {%1, %1};" : "=l"(r) : "f"(v)); return r;
}
__device__ __forceinline__ void ffma2(ull& d, ull a, ull b) { // d = a*b + d (2-wide)
    asm("fma.rn.f32x2 %0, %1, %2, %0;" : "+l"(d) : "l"(a), "l"(b));
}
__device__ __forceinline__ ull mul2(ull a, ull b) {
    ull r; asm("mul.rn.f32x2 %0, %1, %2;" : "=l"(r) : "l"(a), "l"(b)); return r;
}
__device__ __forceinline__ float2 up2(ull v) {               // unpack {lo,hi}
    float2 f; asm("mov.b64 {%0, %1}, %2;" : "=f"(f.x), "=f"(f.y) : "l"(v)); return f;
}

// =================================================================================
// Kernel A: fused QKV projections. 128x128x16 tiled GEMM, 8x8 per thread, FFMA2.
// grid (6, 64, 3), block 256.
// =================================================================================
__global__ void __launch_bounds__(256) qkv_gemm(const float* __restrict__ x,
                                                const float* __restrict__ ctxin,
                                                const float* __restrict__ Wq,
                                                const float* __restrict__ Wk,
                                                const float* __restrict__ Wv)
{
    const int which = blockIdx.z;
    const float* A = (which == 0) ? x : ctxin;
    const float* W = (which == 0) ? Wq : (which == 1 ? Wk : Wv);
    float* Out = (which == 0) ? g_q : (which == 1 ? g_k : g_v);

    const int n0 = blockIdx.x * 128;
    const int m0 = blockIdx.y * 128;
    const int tid = threadIdx.x;

    __shared__ float As[16][128];
    __shared__ float Bs[16][128];

    ull acc[8][4];
#pragma unroll
    for (int i = 0; i < 8; i++)
#pragma unroll
        for (int j = 0; j < 4; j++) acc[i][j] = 0ull;

    const int tm = (tid >> 4) * 8;
    const int tn = (tid & 15) * 8;

    for (int k0 = 0; k0 < CC; k0 += 16) {
#pragma unroll
        for (int i = 0; i < 2; i++) {
            int q = tid * 2 + i;
            int row = q >> 2;
            int cq  = q & 3;
            float4 v = *(const float4*)(&A[(size_t)(m0 + row) * CC + k0 + cq * 4]);
            As[cq*4+0][row] = v.x;
            As[cq*4+1][row] = v.y;
            As[cq*4+2][row] = v.z;
            As[cq*4+3][row] = v.w;
        }
#pragma unroll
        for (int i = 0; i < 2; i++) {
            int q = tid * 2 + i;
            int row = q >> 5;
            int cq  = q & 31;
            *(float4*)(&Bs[row][cq*4]) =
                *(const float4*)(&W[(size_t)(k0 + row) * 768 + n0 + cq * 4]);
        }
        __syncthreads();
#pragma unroll
        for (int kk = 0; kk < 16; kk++) {
            float4 a0 = *(const float4*)(&As[kk][tm]);
            float4 a1 = *(const float4*)(&As[kk][tm + 4]);
            ulonglong2 b0 = *(const ulonglong2*)(&Bs[kk][tn]);
            ulonglong2 b1 = *(const ulonglong2*)(&Bs[kk][tn + 4]);
            float a[8] = {a0.x,a0.y,a0.z,a0.w,a1.x,a1.y,a1.z,a1.w};
#pragma unroll
            for (int i = 0; i < 8; i++) {
                ull ap = bc2(a[i]);
                ffma2(acc[i][0], ap, b0.x);
                ffma2(acc[i][1], ap, b0.y);
                ffma2(acc[i][2], ap, b1.x);
                ffma2(acc[i][3], ap, b1.y);
            }
        }
        __syncthreads();
    }

#pragma unroll
    for (int i = 0; i < 8; i++) {
        float2 p0 = up2(acc[i][0]), p1 = up2(acc[i][1]);
        float2 p2 = up2(acc[i][2]), p3 = up2(acc[i][3]);
        float4 v0 = make_float4(p0.x, p0.y, p1.x, p1.y);
        float4 v1 = make_float4(p2.x, p2.y, p3.x, p3.y);
        *(float4*)(&Out[(size_t)(m0 + tm + i) * 768 + n0 + tn])     = v0;
        *(float4*)(&Out[(size_t)(m0 + tm + i) * 768 + n0 + tn + 4]) = v1;
    }
}

// =================================================================================
// Kernel B: decomposed rel-pos bias tables (unchanged; tiny).
// =================================================================================
__global__ void __launch_bounds__(64) relbias_kernel(const float* __restrict__ rph,
                                                     const float* __restrict__ rpw)
{
    const int bq = blockIdx.x;        // bh*1024 + q
    const int bh = bq >> 10;
    const int q  = bq & 1023;
    const int b = bh / HH, h = bh % HH;
    const int i = q >> 5, j = q & 31;
    const int t = threadIdx.x;

    __shared__ float qs[64];
    qs[t] = g_q[(size_t)(b * TT + q) * CC + h * DD + t];
    __syncthreads();

    if (t < 32) {
        const float* tab = rph + (size_t)(i - t + 31) * DD;
        float acc = 0.0f;
#pragma unroll
        for (int c = 0; c < DD; c++) acc = fmaf(qs[c], tab[c], acc);
        g_relh[(size_t)bq * 32 + t] = acc;
    } else {
        const int kw = t - 32;
        const float* tab = rpw + (size_t)(j - kw + 31) * DD;
        float acc = 0.0f;
#pragma unroll
        for (int c = 0; c < DD; c++) acc = fmaf(qs[c], tab[c], acc);
        g_relw[(size_t)bq * 32 + kw] = acc;
    }
}

// =================================================================================
// Kernel C: fused flash attention. Per block: one (bh, 64-row q-tile).
//   S = QK^T*scale + bias; online softmax; O += P V. No materialized attention.
// grid (16, 96), block 256 (16x16 thread tiles, 4x4 outputs each). Dynamic smem.
// =================================================================================
#define QS 68   // padded stride (floats) for transposed Q/K tiles

struct __align__(16) SmemFlash {
    float Qs[64][QS];     // [d][m]
    float Ks[64][QS];     // [d][n]
    float Vs[64][64];     // [k][d]
    float Ps[64][64];     // [m][k]
    float relh[64][32];   // [m local][kh]
    float relw[64][32];   // [m local][kw]
};

__global__ void __launch_bounds__(256) flash_attn()
{
    extern __shared__ char smem_raw[];
    SmemFlash& S = *(SmemFlash*)smem_raw;

    const int z  = blockIdx.y;          // bh
    const int b  = z / HH, h = z % HH;
    const int q0 = blockIdx.x * 64;
    const int tid = threadIdx.x;
    const int tm = (tid >> 4) * 4;      // 4 rows
    const int tn = (tid & 15) * 4;      // 4 cols

    const float* qb = g_q + (size_t)b * TT * CC + h * DD;
    const float* kb = g_k + (size_t)b * TT * CC + h * DD;
    const float* vb = g_v + (size_t)b * TT * CC + h * DD;

    // ---- load Q tile transposed: Qs[d][m] ----
#pragma unroll
    for (int it = 0; it < 4; it++) {
        int idx = tid + it * 256;         // 0..1023 quads
        int row = idx >> 4;               // 0..63
        int cq  = idx & 15;               // d quad
        float4 v = *(const float4*)(&qb[(size_t)(q0 + row) * CC + cq * 4]);
        S.Qs[cq*4+0][row] = v.x;
        S.Qs[cq*4+1][row] = v.y;
        S.Qs[cq*4+2][row] = v.z;
        S.Qs[cq*4+3][row] = v.w;
    }
    // ---- load rel bias slices for these 64 q rows ----
#pragma unroll
    for (int it = 0; it < 2; it++) {
        int idx = tid + it * 256;         // 0..511 quads (64*32/4)
        int row = idx >> 3;
        int c4  = idx & 7;
        *(float4*)(&S.relh[row][c4*4]) =
            *(const float4*)(&g_relh[((size_t)z * TT + q0 + row) * 32 + c4 * 4]);
        *(float4*)(&S.relw[row][c4*4]) =
            *(const float4*)(&g_relw[((size_t)z * TT + q0 + row) * 32 + c4 * 4]);
    }

    float m_i[4], l_i[4];
    ull   o[4][2];
#pragma unroll
    for (int i = 0; i < 4; i++) {
        m_i[i] = -INFINITY; l_i[i] = 0.0f;
        o[i][0] = 0ull; o[i][1] = 0ull;
    }

    for (int kt = 0; kt < 16; kt++) {
        const int k0 = kt * 64;
        __syncthreads();   // prior PV readers done before K/V overwrite
        // ---- load K tile transposed Ks[d][n], V tile natural Vs[k][d] ----
#pragma unroll
        for (int it = 0; it < 4; it++) {
            int idx = tid + it * 256;
            int row = idx >> 4;
            int cq  = idx & 15;
            float4 v = *(const float4*)(&kb[(size_t)(k0 + row) * CC + cq * 4]);
            S.Ks[cq*4+0][row] = v.x;
            S.Ks[cq*4+1][row] = v.y;
            S.Ks[cq*4+2][row] = v.z;
            S.Ks[cq*4+3][row] = v.w;
            *(float4*)(&S.Vs[row][cq*4]) =
                *(const float4*)(&vb[(size_t)(k0 + row) * CC + cq * 4]);
        }
        __syncthreads();

        // ---- S = Q K^T (4x4 per thread, FFMA2) ----
        ull accs[4][2];
#pragma unroll
        for (int i = 0; i < 4; i++) { accs[i][0] = 0ull; accs[i][1] = 0ull; }
#pragma unroll
        for (int d = 0; d < 64; d++) {
            float4 a4 = *(const float4*)(&S.Qs[d][tm]);
            ulonglong2 bA = *(const ulonglong2*)(&S.Ks[d][tn]);
            ull a0 = bc2(a4.x), a1 = bc2(a4.y), a2 = bc2(a4.z), a3 = bc2(a4.w);
            ffma2(accs[0][0], a0, bA.x); ffma2(accs[0][1], a0, bA.y);
            ffma2(accs[1][0], a1, bA.x); ffma2(accs[1][1], a1, bA.y);
            ffma2(accs[2][0], a2, bA.x); ffma2(accs[2][1], a2, bA.y);
            ffma2(accs[3][0], a3, bA.x); ffma2(accs[3][1], a3, bA.y);
        }

        // ---- scale + rel-pos bias ----
        float sc[4][4];
#pragma unroll
        for (int i = 0; i < 4; i++) {
            float2 p0 = up2(accs[i][0]), p1 = up2(accs[i][1]);
            sc[i][0] = p0.x; sc[i][1] = p0.y; sc[i][2] = p1.x; sc[i][3] = p1.y;
#pragma unroll
            for (int j = 0; j < 4; j++) {
                int kloc = tn + j;
                int khj  = kt * 2 + (kloc >> 5);
                sc[i][j] = sc[i][j] * SCALE
                         + S.relh[tm + i][khj]
                         + S.relw[tm + i][kloc & 31];
            }
        }

        // ---- online softmax (row spread over 16 lanes; xor<16 stays in group) ----
#pragma unroll
        for (int i = 0; i < 4; i++) {
            float rm = fmaxf(fmaxf(sc[i][0], sc[i][1]), fmaxf(sc[i][2], sc[i][3]));
#pragma unroll
            for (int off = 1; off < 16; off <<= 1)
                rm = fmaxf(rm, __shfl_xor_sync(0xffffffffu, rm, off));
            float mn = fmaxf(m_i[i], rm);
            float corr = __expf(m_i[i] - mn);
            m_i[i] = mn;
            float rs = 0.0f;
#pragma unroll
            for (int j = 0; j < 4; j++) {
                float p = __expf(sc[i][j] - mn);
                sc[i][j] = p;
                rs += p;
            }
#pragma unroll
            for (int off = 1; off < 16; off <<= 1)
                rs += __shfl_xor_sync(0xffffffffu, rs, off);
            l_i[i] = l_i[i] * corr + rs;
            ull cp = bc2(corr);
            o[i][0] = mul2(o[i][0], cp);
            o[i][1] = mul2(o[i][1], cp);
            *(float4*)(&S.Ps[tm + i][tn]) = make_float4(sc[i][0], sc[i][1], sc[i][2], sc[i][3]);
        }
        __syncthreads();

        // ---- O += P V ----
#pragma unroll
        for (int k = 0; k < 64; k++) {
            ulonglong2 bV = *(const ulonglong2*)(&S.Vs[k][tn]);
            ull a0 = bc2(S.Ps[tm + 0][k]);
            ull a1 = bc2(S.Ps[tm + 1][k]);
            ull a2 = bc2(S.Ps[tm + 2][k]);
            ull a3 = bc2(S.Ps[tm + 3][k]);
            ffma2(o[0][0], a0, bV.x); ffma2(o[0][1], a0, bV.y);
            ffma2(o[1][0], a1, bV.x); ffma2(o[1][1], a1, bV.y);
            ffma2(o[2][0], a2, bV.x); ffma2(o[2][1], a2, bV.y);
            ffma2(o[3][0], a3, bV.x); ffma2(o[3][1], a3, bV.y);
        }
    }

    // ---- normalize + write ctx ----
#pragma unroll
    for (int i = 0; i < 4; i++) {
        float inv = 1.0f / l_i[i];
        float2 u0 = up2(o[i][0]), u1 = up2(o[i][1]);
        float4 r = make_float4(u0.x * inv, u0.y * inv, u1.x * inv, u1.y * inv);
        *(float4*)(&g_ctx[(size_t)(b * TT + q0 + tm + i) * CC + h * DD + tn]) = r;
    }
}

// =================================================================================
// Kernel D: out = ctx @ Wo + bo (FFMA2). grid (6, 64), block 256.
// =================================================================================
__global__ void __launch_bounds__(256) out_gemm(const float* __restrict__ Wo,
                                                const float* __restrict__ bo,
                                                float* __restrict__ out)
{
    const int n0 = blockIdx.x * 128;
    const int m0 = blockIdx.y * 128;
    const int tid = threadIdx.x;

    __shared__ float As[16][128];
    __shared__ float Bs[16][128];

    ull acc[8][4];
#pragma unroll
    for (int i = 0; i < 8; i++)
#pragma unroll
        for (int j = 0; j < 4; j++) acc[i][j] = 0ull;

    const int tm = (tid >> 4) * 8;
    const int tn = (tid & 15) * 8;

    for (int k0 = 0; k0 < 768; k0 += 16) {
#pragma unroll
        for (int i = 0; i < 2; i++) {
            int q = tid * 2 + i;
            int row = q >> 2;
            int cq  = q & 3;
            float4 v = *(const float4*)(&g_ctx[(size_t)(m0 + row) * CC + k0 + cq * 4]);
            As[cq*4+0][row] = v.x;
            As[cq*4+1][row] = v.y;
            As[cq*4+2][row] = v.z;
            As[cq*4+3][row] = v.w;
        }
#pragma unroll
        for (int i = 0; i < 2; i++) {
            int q = tid * 2 + i;
            int row = q >> 5;
            int cq  = q & 31;
            *(float4*)(&Bs[row][cq*4]) =
                *(const float4*)(&Wo[(size_t)(k0 + row) * CC + n0 + cq * 4]);
        }
        __syncthreads();
#pragma unroll
        for (int kk = 0; kk < 16; kk++) {
            float4 a0 = *(const float4*)(&As[kk][tm]);
            float4 a1 = *(const float4*)(&As[kk][tm + 4]);
            ulonglong2 b0 = *(const ulonglong2*)(&Bs[kk][tn]);
            ulonglong2 b1 = *(const ulonglong2*)(&Bs[kk][tn + 4]);
            float a[8] = {a0.x,a0.y,a0.z,a0.w,a1.x,a1.y,a1.z,a1.w};
#pragma unroll
            for (int i = 0; i < 8; i++) {
                ull ap = bc2(a[i]);
                ffma2(acc[i][0], ap, b0.x);
                ffma2(acc[i][1], ap, b0.y);
                ffma2(acc[i][2], ap, b1.x);
                ffma2(acc[i][3], ap, b1.y);
            }
        }
        __syncthreads();
    }

#pragma unroll
    for (int i = 0; i < 8; i++) {
        float2 p0 = up2(acc[i][0]), p1 = up2(acc[i][1]);
        float2 p2 = up2(acc[i][2]), p3 = up2(acc[i][3]);
        float4 v0, v1;
        v0.x = p0.x + bo[n0+tn+0]; v0.y = p0.y + bo[n0+tn+1];
        v0.z = p1.x + bo[n0+tn+2]; v0.w = p1.y + bo[n0+tn+3];
        v1.x = p2.x + bo[n0+tn+4]; v1.y = p2.y + bo[n0+tn+5];
        v1.z = p3.x + bo[n0+tn+6]; v1.w = p3.y + bo[n0+tn+7];
        *(float4*)(&out[(size_t)(m0 + tm + i) * CC + n0 + tn])     = v0;
        *(float4*)(&out[(size_t)(m0 + tm + i) * CC + n0 + tn + 4]) = v1;
    }
}

// =================================================================================
extern "C" void kernel_launch(void* const* d_in, const int* in_sizes, int n_in,
                              void* d_out, int out_size)
{
    const float* x   = (const float*)d_in[0];
    const float* ctx = (const float*)d_in[1];
    const float* Wq  = (const float*)d_in[2];
    const float* Wk  = (const float*)d_in[3];
    const float* Wv  = (const float*)d_in[4];
    const float* Wo  = (const float*)d_in[5];
    const float* bo  = (const float*)d_in[6];
    const float* rph = (const float*)d_in[7];
    const float* rpw = (const float*)d_in[8];
    float* out = (float*)d_out;

    static_assert(sizeof(SmemFlash) <= 96 * 1024, "smem");
    cudaFuncSetAttribute(flash_attn, cudaFuncAttributeMaxDynamicSharedMemorySize,
                         (int)sizeof(SmemFlash));

    qkv_gemm<<<dim3(6, 64, 3), 256>>>(x, ctx, Wq, Wk, Wv);
    relbias_kernel<<<BH * TT, 64>>>(rph, rpw);
    flash_attn<<<dim3(16, 96), 256, sizeof(SmemFlash)>>>();
    out_gemm<<<dim3(6, 64), 256>>>(Wo, bo, out);
}

// round 6
// speedup vs baseline: 1.1793x; 1.0420x over previous
#include <cuda_runtime.h>
#include <math.h>

#define BB 8
#define TT 1024
#define CC 768
#define HH 12
#define DD 64
#define BH (BB*HH)          // 96
#define SCALE 0.125f

// ---------------- scratch (device globals; no allocation allowed) ----------------
__device__ float g_q[BB*TT*CC];
__device__ float g_k[BB*TT*CC];
__device__ float g_v[BB*TT*CC];
__device__ float g_ctx[BB*TT*CC];
__device__ float g_relh[BH*TT*32];               // (bh, q, kh)
__device__ float g_relw[BH*TT*32];               // (bh, q, kw)
__device__ float g_att[(size_t)BH*TT*TT];        // raw biased scores (402 MB)
__device__ float g_m[BH*TT];                     // row max
__device__ float g_l[BH*TT];                     // row sum-exp

// ---------------- packed fp32x2 (FFMA2; PTX-only) --------------------------------
typedef unsigned long long ull;
__device__ __forceinline__ ull bc2(float v) {
    ull r; asm("mov.b64 %0, {%1, %1};" : "=l"(r) : "f"(v)); return r;
}
__device__ __forceinline__ void ffma2(ull& d, ull a, ull b) {
    asm("fma.rn.f32x2 %0, %1, %2, %0;" : "+l"(d) : "l"(a), "l"(b));
}
__device__ __forceinline__ float2 up2(ull v) {
    float2 f; asm("mov.b64 {%0, %1}, %2;" : "=f"(f.x), "=f"(f.y) : "l"(v)); return f;
}

#define LDA 132      // padded m-stride for transposed A tiles
#define LDB 68       // padded n-stride for natural B tiles

struct SmemG { float As[2][32][LDA]; float Bs[2][32][LDB]; };   // 51200 B
struct SmemS {                                                   // 101376 B
    float Qs[64][LDA];
    float Kt[2][64][LDB];
    float rh[128][32];
    float rw[128][32];
};

// one BK=32 chunk: 8m x 4n per thread, FFMA2
__device__ __forceinline__ void gemm_chunk(const float (*As)[LDA], const float (*Bs)[LDB],
                                           int tm, int tn, ull acc[8][2]) {
#pragma unroll 8
    for (int kk = 0; kk < 32; kk++) {
        float4 a0 = *(const float4*)&As[kk][tm];
        float4 a1 = *(const float4*)&As[kk][tm + 4];
        ulonglong2 bv = *(const ulonglong2*)&Bs[kk][tn];
        float av[8] = {a0.x, a0.y, a0.z, a0.w, a1.x, a1.y, a1.z, a1.w};
#pragma unroll
        for (int i = 0; i < 8; i++) {
            ull ap = bc2(av[i]);
            ffma2(acc[i][0], ap, bv.x);
            ffma2(acc[i][1], ap, bv.y);
        }
    }
}

// =================================================================================
// qkv: {g_q,g_k,g_v} = {x,ctx,ctx} @ {Wq,Wk,Wv}. Tile 128x64, K=768.
// grid (12, 64, 3), 256 thr. Double-buffered via register staging.
// =================================================================================
__global__ void __launch_bounds__(256) qkv_gemm(const float* __restrict__ x,
                                                const float* __restrict__ ctxin,
                                                const float* __restrict__ Wq,
                                                const float* __restrict__ Wk,
                                                const float* __restrict__ Wv)
{
    extern __shared__ char smraw[];
    SmemG& S = *(SmemG*)smraw;
    const int z = blockIdx.z;
    const float* A = (z == 0) ? x : ctxin;
    const float* W = (z == 0) ? Wq : (z == 1 ? Wk : Wv);
    float* Out = (z == 0) ? g_q : (z == 1 ? g_k : g_v);

    const int tid = threadIdx.x;
    const int n0 = blockIdx.x * 64, m0 = blockIdx.y * 128;
    const int tm = (tid >> 4) * 8, tn = (tid & 15) * 4;
    const int ar = tid >> 3, akq = (tid & 7) * 4;
    const int br = tid >> 4, bnq = (tid & 15) * 4;

    ull acc[8][2];
#pragma unroll
    for (int i = 0; i < 8; i++) { acc[i][0] = 0ull; acc[i][1] = 0ull; }

    float4 fa[4], fb[2];
#pragma unroll
    for (int i = 0; i < 4; i++)
        fa[i] = *(const float4*)&A[(size_t)(m0 + ar + 32 * i) * CC + akq];
#pragma unroll
    for (int i = 0; i < 2; i++)
        fb[i] = *(const float4*)&W[(size_t)(br + 16 * i) * CC + n0 + bnq];
#pragma unroll
    for (int i = 0; i < 4; i++) {
        S.As[0][akq+0][ar+32*i] = fa[i].x; S.As[0][akq+1][ar+32*i] = fa[i].y;
        S.As[0][akq+2][ar+32*i] = fa[i].z; S.As[0][akq+3][ar+32*i] = fa[i].w;
    }
#pragma unroll
    for (int i = 0; i < 2; i++) *(float4*)&S.Bs[0][br + 16*i][bnq] = fb[i];
    __syncthreads();

    for (int kt = 0; kt < 24; kt++) {
        if (kt < 23) {
            const int k0 = (kt + 1) * 32;
#pragma unroll
            for (int i = 0; i < 4; i++)
                fa[i] = *(const float4*)&A[(size_t)(m0 + ar + 32 * i) * CC + k0 + akq];
#pragma unroll
            for (int i = 0; i < 2; i++)
                fb[i] = *(const float4*)&W[(size_t)(k0 + br + 16 * i) * CC + n0 + bnq];
        }
        gemm_chunk(S.As[kt & 1], S.Bs[kt & 1], tm, tn, acc);
        if (kt < 23) {
            __syncthreads();
            const int nb = (kt + 1) & 1;
#pragma unroll
            for (int i = 0; i < 4; i++) {
                S.As[nb][akq+0][ar+32*i] = fa[i].x; S.As[nb][akq+1][ar+32*i] = fa[i].y;
                S.As[nb][akq+2][ar+32*i] = fa[i].z; S.As[nb][akq+3][ar+32*i] = fa[i].w;
            }
#pragma unroll
            for (int i = 0; i < 2; i++) *(float4*)&S.Bs[nb][br + 16*i][bnq] = fb[i];
            __syncthreads();
        }
    }
#pragma unroll
    for (int i = 0; i < 8; i++) {
        float2 u0 = up2(acc[i][0]), u1 = up2(acc[i][1]);
        *(float4*)&Out[(size_t)(m0 + tm + i) * CC + n0 + tn] =
            make_float4(u0.x, u0.y, u1.x, u1.y);
    }
}

// =================================================================================
// relbias (validated rounds 1-2)
// =================================================================================
__global__ void __launch_bounds__(64) relbias_kernel(const float* __restrict__ rph,
                                                     const float* __restrict__ rpw)
{
    const int bq = blockIdx.x;
    const int bh = bq >> 10;
    const int q  = bq & 1023;
    const int b = bh / HH, h = bh % HH;
    const int i = q >> 5, j = q & 31;
    const int t = threadIdx.x;

    __shared__ float qs[64];
    qs[t] = g_q[(size_t)(b * TT + q) * CC + h * DD + t];
    __syncthreads();

    if (t < 32) {
        const float* tab = rph + (size_t)(i - t + 31) * DD;
        float acc = 0.0f;
#pragma unroll
        for (int c = 0; c < DD; c++) acc = fmaf(qs[c], tab[c], acc);
        g_relh[(size_t)bq * 32 + t] = acc;
    } else {
        const int kw = t - 32;
        const float* tab = rpw + (size_t)(j - kw + 31) * DD;
        float acc = 0.0f;
#pragma unroll
        for (int c = 0; c < DD; c++) acc = fmaf(qs[c], tab[c], acc);
        g_relw[(size_t)bq * 32 + kw] = acc;
    }
}

// =================================================================================
// scores: per block (128 q-rows, bh) stream all 16 key-tiles of 64.
// Writes raw biased S to g_att; tracks online row max m and sum-exp l -> g_m/g_l.
// grid (8, 96), 256 thr.
// =================================================================================
__global__ void __launch_bounds__(256) scores_gemm()
{
    extern __shared__ char smraw[];
    SmemS& S = *(SmemS*)smraw;
    const int z = blockIdx.y, b = z / HH, h = z % HH;
    const int m0 = blockIdx.x * 128;
    const int tid = threadIdx.x;
    const int tm = (tid >> 4) * 8, tn = (tid & 15) * 4;

    // Q tile transposed [d][m] (once)
    const float* qb = g_q + (size_t)(b * TT + m0) * CC + h * DD;
#pragma unroll
    for (int i = 0; i < 8; i++) {
        int idx = tid + 256 * i;                 // 2048 quads
        int qm = idx >> 4, qd = (idx & 15) * 4;
        float4 v = *(const float4*)&qb[(size_t)qm * CC + qd];
        S.Qs[qd+0][qm] = v.x; S.Qs[qd+1][qm] = v.y;
        S.Qs[qd+2][qm] = v.z; S.Qs[qd+3][qm] = v.w;
    }
    // rel tables for these rows
#pragma unroll
    for (int i = 0; i < 4; i++) {
        int idx = tid + 256 * i;                 // 1024 quads
        int row = idx >> 3, c = (idx & 7) * 4;
        *(float4*)&S.rh[row][c] = *(const float4*)&g_relh[((size_t)z*TT + m0 + row)*32 + c];
        *(float4*)&S.rw[row][c] = *(const float4*)&g_relw[((size_t)z*TT + m0 + row)*32 + c];
    }

    const float* kb = g_k + (size_t)(b * TT) * CC + h * DD;
    const int kr = tid >> 4, kd = (tid & 15) * 4;
    float4 fk[4];
#pragma unroll
    for (int i = 0; i < 4; i++)
        fk[i] = *(const float4*)&kb[(size_t)(kr + 16 * i) * CC + kd];
#pragma unroll
    for (int i = 0; i < 4; i++) {
        S.Kt[0][kd+0][kr+16*i] = fk[i].x; S.Kt[0][kd+1][kr+16*i] = fk[i].y;
        S.Kt[0][kd+2][kr+16*i] = fk[i].z; S.Kt[0][kd+3][kr+16*i] = fk[i].w;
    }
    __syncthreads();

    float m_i[8], l_i[8];
#pragma unroll
    for (int i = 0; i < 8; i++) { m_i[i] = -INFINITY; l_i[i] = 0.0f; }

    for (int nt = 0; nt < 16; nt++) {
        if (nt < 15) {
            const int kbase = (nt + 1) * 64;
#pragma unroll
            for (int i = 0; i < 4; i++)
                fk[i] = *(const float4*)&kb[(size_t)(kbase + kr + 16 * i) * CC + kd];
        }

        ull acc[8][2];
#pragma unroll
        for (int i = 0; i < 8; i++) { acc[i][0] = 0ull; acc[i][1] = 0ull; }
        const float (*Kc)[LDB] = S.Kt[nt & 1];
#pragma unroll 8
        for (int kk = 0; kk < 64; kk++) {
            float4 a0 = *(const float4*)&S.Qs[kk][tm];
            float4 a1 = *(const float4*)&S.Qs[kk][tm + 4];
            ulonglong2 bv = *(const ulonglong2*)&Kc[kk][tn];
            float av[8] = {a0.x, a0.y, a0.z, a0.w, a1.x, a1.y, a1.z, a1.w};
#pragma unroll
            for (int i = 0; i < 8; i++) {
                ull ap = bc2(av[i]);
                ffma2(acc[i][0], ap, bv.x);
                ffma2(acc[i][1], ap, bv.y);
            }
        }

        // epilogue: bias + online softmax stats + store raw S
        const int khi = nt * 2 + (tn >> 5);
        const int tnm = tn & 31;
#pragma unroll
        for (int i = 0; i < 8; i++) {
            const int row = tm + i;
            float2 u0 = up2(acc[i][0]), u1 = up2(acc[i][1]);
            const float rhv = S.rh[row][khi];
            float s0 = fmaf(u0.x, SCALE, rhv + S.rw[row][tnm]);
            float s1 = fmaf(u0.y, SCALE, rhv + S.rw[row][tnm + 1]);
            float s2 = fmaf(u1.x, SCALE, rhv + S.rw[row][tnm + 2]);
            float s3 = fmaf(u1.y, SCALE, rhv + S.rw[row][tnm + 3]);
            float tmax = fmaxf(fmaxf(s0, s1), fmaxf(s2, s3));
#pragma unroll
            for (int o = 1; o < 16; o <<= 1)
                tmax = fmaxf(tmax, __shfl_xor_sync(0xffffffffu, tmax, o));
            const float mn = fmaxf(m_i[i], tmax);
            const float corr = __expf(m_i[i] - mn);
            float rs = __expf(s0 - mn) + __expf(s1 - mn) + __expf(s2 - mn) + __expf(s3 - mn);
#pragma unroll
            for (int o = 1; o < 16; o <<= 1)
                rs += __shfl_xor_sync(0xffffffffu, rs, o);
            l_i[i] = l_i[i] * corr + rs;
            m_i[i] = mn;
            *(float4*)&g_att[((size_t)z * TT + m0 + row) * TT + nt * 64 + tn] =
                make_float4(s0, s1, s2, s3);
        }

        if (nt < 15) {
            __syncthreads();
            const int nb = (nt + 1) & 1;
#pragma unroll
            for (int i = 0; i < 4; i++) {
                S.Kt[nb][kd+0][kr+16*i] = fk[i].x; S.Kt[nb][kd+1][kr+16*i] = fk[i].y;
                S.Kt[nb][kd+2][kr+16*i] = fk[i].z; S.Kt[nb][kd+3][kr+16*i] = fk[i].w;
            }
            __syncthreads();
        }
    }

    if ((tid & 15) == 0) {
#pragma unroll
        for (int i = 0; i < 8; i++) {
            g_m[z * TT + m0 + tm + i] = m_i[i];
            g_l[z * TT + m0 + tm + i] = l_i[i];
        }
    }
}

// =================================================================================
// pv: ctx = softmax(S) @ V. A-fill applies exp(s - m); epilogue applies 1/l.
// grid (8, 96), 256 thr. Tile 128x64, K=1024.
// =================================================================================
__global__ void __launch_bounds__(256) pv_gemm()
{
    extern __shared__ char smraw[];
    SmemG& S = *(SmemG*)smraw;
    const int z = blockIdx.y, b = z / HH, h = z % HH;
    const int m0 = blockIdx.x * 128;
    const int tid = threadIdx.x;
    const int tm = (tid >> 4) * 8, tn = (tid & 15) * 4;
    const int ar = tid >> 3, akq = (tid & 7) * 4;
    const int br = tid >> 4, bnq = (tid & 15) * 4;

    const float* att = g_att + ((size_t)z * TT + m0) * TT;
    const float* vb  = g_v + (size_t)(b * TT) * CC + h * DD;

    float mrow[4];
#pragma unroll
    for (int i = 0; i < 4; i++) mrow[i] = g_m[z * TT + m0 + ar + 32 * i];

    ull acc[8][2];
#pragma unroll
    for (int i = 0; i < 8; i++) { acc[i][0] = 0ull; acc[i][1] = 0ull; }

    float4 fa[4], fb[2];
#pragma unroll
    for (int i = 0; i < 4; i++)
        fa[i] = *(const float4*)&att[(size_t)(ar + 32 * i) * TT + akq];
#pragma unroll
    for (int i = 0; i < 2; i++)
        fb[i] = *(const float4*)&vb[(size_t)(br + 16 * i) * CC + bnq];
#pragma unroll
    for (int i = 0; i < 4; i++) {
        S.As[0][akq+0][ar+32*i] = __expf(fa[i].x - mrow[i]);
        S.As[0][akq+1][ar+32*i] = __expf(fa[i].y - mrow[i]);
        S.As[0][akq+2][ar+32*i] = __expf(fa[i].z - mrow[i]);
        S.As[0][akq+3][ar+32*i] = __expf(fa[i].w - mrow[i]);
    }
#pragma unroll
    for (int i = 0; i < 2; i++) *(float4*)&S.Bs[0][br + 16*i][bnq] = fb[i];
    __syncthreads();

    for (int kt = 0; kt < 32; kt++) {
        if (kt < 31) {
            const int k0 = (kt + 1) * 32;
#pragma unroll
            for (int i = 0; i < 4; i++)
                fa[i] = *(const float4*)&att[(size_t)(ar + 32 * i) * TT + k0 + akq];
#pragma unroll
            for (int i = 0; i < 2; i++)
                fb[i] = *(const float4*)&vb[(size_t)(k0 + br + 16 * i) * CC + bnq];
        }
        gemm_chunk(S.As[kt & 1], S.Bs[kt & 1], tm, tn, acc);
        if (kt < 31) {
            __syncthreads();
            const int nb = (kt + 1) & 1;
#pragma unroll
            for (int i = 0; i < 4; i++) {
                S.As[nb][akq+0][ar+32*i] = __expf(fa[i].x - mrow[i]);
                S.As[nb][akq+1][ar+32*i] = __expf(fa[i].y - mrow[i]);
                S.As[nb][akq+2][ar+32*i] = __expf(fa[i].z - mrow[i]);
                S.As[nb][akq+3][ar+32*i] = __expf(fa[i].w - mrow[i]);
            }
#pragma unroll
            for (int i = 0; i < 2; i++) *(float4*)&S.Bs[nb][br + 16*i][bnq] = fb[i];
            __syncthreads();
        }
    }

#pragma unroll
    for (int i = 0; i < 8; i++) {
        const float invl = 1.0f / g_l[z * TT + m0 + tm + i];
        float2 u0 = up2(acc[i][0]), u1 = up2(acc[i][1]);
        *(float4*)&g_ctx[(size_t)(b * TT + m0 + tm + i) * CC + h * DD + tn] =
            make_float4(u0.x * invl, u0.y * invl, u1.x * invl, u1.y * invl);
    }
}

// =================================================================================
// out: out = ctx @ Wo + bo. grid (12, 64), same skeleton as qkv.
// =================================================================================
__global__ void __launch_bounds__(256) out_gemm(const float* __restrict__ Wo,
                                                const float* __restrict__ bo,
                                                float* __restrict__ Out)
{
    extern __shared__ char smraw[];
    SmemG& S = *(SmemG*)smraw;
    const int tid = threadIdx.x;
    const int n0 = blockIdx.x * 64, m0 = blockIdx.y * 128;
    const int tm = (tid >> 4) * 8, tn = (tid & 15) * 4;
    const int ar = tid >> 3, akq = (tid & 7) * 4;
    const int br = tid >> 4, bnq = (tid & 15) * 4;

    ull acc[8][2];
#pragma unroll
    for (int i = 0; i < 8; i++) { acc[i][0] = 0ull; acc[i][1] = 0ull; }

    float4 fa[4], fb[2];
#pragma unroll
    for (int i = 0; i < 4; i++)
        fa[i] = *(const float4*)&g_ctx[(size_t)(m0 + ar + 32 * i) * CC + akq];
#pragma unroll
    for (int i = 0; i < 2; i++)
        fb[i] = *(const float4*)&Wo[(size_t)(br + 16 * i) * CC + n0 + bnq];
#pragma unroll
    for (int i = 0; i < 4; i++) {
        S.As[0][akq+0][ar+32*i] = fa[i].x; S.As[0][akq+1][ar+32*i] = fa[i].y;
        S.As[0][akq+2][ar+32*i] = fa[i].z; S.As[0][akq+3][ar+32*i] = fa[i].w;
    }
#pragma unroll
    for (int i = 0; i < 2; i++) *(float4*)&S.Bs[0][br + 16*i][bnq] = fb[i];
    __syncthreads();

    for (int kt = 0; kt < 24; kt++) {
        if (kt < 23) {
            const int k0 = (kt + 1) * 32;
#pragma unroll
            for (int i = 0; i < 4; i++)
                fa[i] = *(const float4*)&g_ctx[(size_t)(m0 + ar + 32 * i) * CC + k0 + akq];
#pragma unroll
            for (int i = 0; i < 2; i++)
                fb[i] = *(const float4*)&Wo[(size_t)(k0 + br + 16 * i) * CC + n0 + bnq];
        }
        gemm_chunk(S.As[kt & 1], S.Bs[kt & 1], tm, tn, acc);
        if (kt < 23) {
            __syncthreads();
            const int nb = (kt + 1) & 1;
#pragma unroll
            for (int i = 0; i < 4; i++) {
                S.As[nb][akq+0][ar+32*i] = fa[i].x; S.As[nb][akq+1][ar+32*i] = fa[i].y;
                S.As[nb][akq+2][ar+32*i] = fa[i].z; S.As[nb][akq+3][ar+32*i] = fa[i].w;
            }
#pragma unroll
            for (int i = 0; i < 2; i++) *(float4*)&S.Bs[nb][br + 16*i][bnq] = fb[i];
            __syncthreads();
        }
    }

    const float4 bv0 = *(const float4*)&bo[n0 + tn];
#pragma unroll
    for (int i = 0; i < 8; i++) {
        float2 u0 = up2(acc[i][0]), u1 = up2(acc[i][1]);
        *(float4*)&Out[(size_t)(m0 + tm + i) * CC + n0 + tn] =
            make_float4(u0.x + bv0.x, u0.y + bv0.y, u1.x + bv0.z, u1.y + bv0.w);
    }
}

// =================================================================================
extern "C" void kernel_launch(void* const* d_in, const int* in_sizes, int n_in,
                              void* d_out, int out_size)
{
    const float* x   = (const float*)d_in[0];
    const float* ctx = (const float*)d_in[1];
    const float* Wq  = (const float*)d_in[2];
    const float* Wk  = (const float*)d_in[3];
    const float* Wv  = (const float*)d_in[4];
    const float* Wo  = (const float*)d_in[5];
    const float* bo  = (const float*)d_in[6];
    const float* rph = (const float*)d_in[7];
    const float* rpw = (const float*)d_in[8];
    float* out = (float*)d_out;

    cudaFuncSetAttribute(qkv_gemm,    cudaFuncAttributeMaxDynamicSharedMemorySize, (int)sizeof(SmemG));
    cudaFuncSetAttribute(out_gemm,    cudaFuncAttributeMaxDynamicSharedMemorySize, (int)sizeof(SmemG));
    cudaFuncSetAttribute(pv_gemm,     cudaFuncAttributeMaxDynamicSharedMemorySize, (int)sizeof(SmemG));
    cudaFuncSetAttribute(scores_gemm, cudaFuncAttributeMaxDynamicSharedMemorySize, (int)sizeof(SmemS));

    qkv_gemm<<<dim3(12, 64, 3), 256, sizeof(SmemG)>>>(x, ctx, Wq, Wk, Wv);
    relbias_kernel<<<BH * TT, 64>>>(rph, rpw);
    scores_gemm<<<dim3(8, 96), 256, sizeof(SmemS)>>>();
    pv_gemm<<<dim3(8, 96), 256, sizeof(SmemG)>>>();
    out_gemm<<<dim3(12, 64), 256, sizeof(SmemG)>>>(Wo, bo, out);
}

// round 7
// speedup vs baseline: 1.2741x; 1.0804x over previous
#include <cuda_runtime.h>
#include <math.h>

#define BB 8
#define TT 1024
#define CC 768
#define HH 12
#define DD 64
#define BH (BB*HH)          // 96
#define BT (BB*TT)          // 8192
#define SCALE 0.125f

// ---------------- scratch (device globals; no allocation allowed) ----------------
__device__ float g_xT[CC*BT];                    // x transposed   [c][m]
__device__ float g_cT[CC*BT];                    // ctx transposed [c][m]
__device__ float g_q [BT*CC];                    // q natural (relbias)
__device__ float g_qT[BH*DD*TT];                 // q  [bh][d][q]
__device__ float g_kT[BH*DD*TT];                 // k  [bh][d][key]
__device__ float g_v [BT*CC];                    // v natural (pv B)
__device__ float g_oT[CC*BT];                    // attention out transposed [c][m]
__device__ float g_relh[BH*TT*32];
__device__ float g_relw[BH*TT*32];
__device__ float g_att[(size_t)BH*TT*TT];        // raw biased scores
__device__ float g_m[BH*TT];
__device__ float g_l[BH*TT];

// ---------------- packed fp32x2 + async helpers ----------------------------------
typedef unsigned long long ull;
__device__ __forceinline__ ull bc2(float v) {
    ull r; asm("mov.b64 %0, {%1, %1};" : "=l"(r) : "f"(v)); return r;
}
__device__ __forceinline__ void ffma2(ull& d, ull a, ull b) {
    asm("fma.rn.f32x2 %0, %1, %2, %0;" : "+l"(d) : "l"(a), "l"(b));
}
__device__ __forceinline__ float2 up2(ull v) {
    float2 f; asm("mov.b64 {%0, %1}, %2;" : "=f"(f.x), "=f"(f.y) : "l"(v)); return f;
}
__device__ __forceinline__ unsigned s2u(const void* p) {
    unsigned a;
    asm("{ .reg .u64 t; cvta.to.shared.u64 t, %1; cvt.u32.u64 %0, t; }" : "=r"(a) : "l"(p));
    return a;
}
__device__ __forceinline__ void cpa16(unsigned dst, const float* src) {
    asm volatile("cp.async.cg.shared.global [%0], [%1], 16;" :: "r"(dst), "l"(src) : "memory");
}
#define CP_COMMIT() asm volatile("cp.async.commit_group;" ::: "memory")
#define CP_WAIT0()  asm volatile("cp.async.wait_group 0;" ::: "memory")
#define CP_WAIT1()  asm volatile("cp.async.wait_group 1;" ::: "memory")

#define LDA 132      // floats, [k][m] tile stride (m=128)
#define LDB 68       // floats, [k][n] tile stride (n=64)

struct SmemG { float As[2][32][LDA]; float Bs[2][32][LDB]; };        // 51200 B
struct SmemS {                                                        // 101376 B
    float Qs[64][LDA];
    float Kt[2][64][LDB];
    float rh[128][32];
    float rw[128][32];
};

// one k-step batch: acc[nj][mpair]  (16 FFMA2, 3 LDS.128, 4 MOV)
#define KSTEP(AS, BS, kk)                                              \
    {                                                                  \
        ulonglong2 a01 = *(const ulonglong2*)&(AS)[kk][tm];            \
        ulonglong2 a23 = *(const ulonglong2*)&(AS)[kk][tm + 4];        \
        float4 bv = *(const float4*)&(BS)[kk][tn];                     \
        ull b0 = bc2(bv.x), b1 = bc2(bv.y), b2 = bc2(bv.z), b3 = bc2(bv.w); \
        ffma2(acc[0][0], a01.x, b0); ffma2(acc[0][1], a01.y, b0);      \
        ffma2(acc[0][2], a23.x, b0); ffma2(acc[0][3], a23.y, b0);      \
        ffma2(acc[1][0], a01.x, b1); ffma2(acc[1][1], a01.y, b1);      \
        ffma2(acc[1][2], a23.x, b1); ffma2(acc[1][3], a23.y, b1);      \
        ffma2(acc[2][0], a01.x, b2); ffma2(acc[2][1], a01.y, b2);      \
        ffma2(acc[2][2], a23.x, b2); ffma2(acc[2][3], a23.y, b2);      \
        ffma2(acc[3][0], a01.x, b3); ffma2(acc[3][1], a01.y, b3);      \
        ffma2(acc[3][2], a23.x, b3); ffma2(acc[3][3], a23.y, b3);      \
    }

// =================================================================================
// transpose_in: xT/cT [c][m] from x/ctx [m][c]. grid (256, 24, 2), block (32,8).
// =================================================================================
__global__ void __launch_bounds__(256) transpose_in(const float* __restrict__ x,
                                                    const float* __restrict__ ctx)
{
    __shared__ float t[32][33];
    const float* src = blockIdx.z ? ctx : x;
    float* dst = blockIdx.z ? g_cT : g_xT;
    const int m0 = blockIdx.x * 32, c0 = blockIdx.y * 32;
    const int tx = threadIdx.x, ty = threadIdx.y;
#pragma unroll
    for (int i = 0; i < 4; i++)
        t[ty + 8 * i][tx] = src[(size_t)(m0 + ty + 8 * i) * CC + c0 + tx];
    __syncthreads();
#pragma unroll
    for (int i = 0; i < 4; i++)
        dst[(size_t)(c0 + ty + 8 * i) * BT + m0 + tx] = t[tx][ty + 8 * i];
}

// =================================================================================
// qkv: {q, k, v} = {xT,cT,cT}^T @ W.  Tile 128x64, BK=32, cp.async pipeline.
// grid (12, 64, 3), 256 thr, 3 CTAs/SM target.
// =================================================================================
__global__ void __launch_bounds__(256, 3) qkv_gemm(const float* __restrict__ Wq,
                                                   const float* __restrict__ Wk,
                                                   const float* __restrict__ Wv)
{
    extern __shared__ char smraw[];
    SmemG& S = *(SmemG*)smraw;
    const unsigned sb = s2u(smraw);
    const int z = blockIdx.z;
    const float* AT = (z == 0) ? g_xT : g_cT;
    const float* W  = (z == 0) ? Wq : (z == 1 ? Wk : Wv);

    const int tid = threadIdx.x;
    const int n0 = blockIdx.x * 64, m0 = blockIdx.y * 128;
    const int tm = (tid >> 4) * 8, tn = (tid & 15) * 4;

    // copy coords
    const int arow = tid >> 6, ac = tid & 63;          // unused helper form
    (void)arow; (void)ac;

    ull acc[4][4];
#pragma unroll
    for (int j = 0; j < 4; j++)
#pragma unroll
        for (int p = 0; p < 4; p++) acc[j][p] = 0ull;

    // ---- issue buffer 0 ----
    {
#pragma unroll
        for (int i = 0; i < 4; i++) {
            int idx = tid + 256 * i;
            int r = idx >> 5, c = idx & 31;
            cpa16(sb + (unsigned)((0 * 32 + r) * LDA + c * 4) * 4,
                  AT + (size_t)r * BT + m0 + c * 4);
        }
#pragma unroll
        for (int i = 0; i < 2; i++) {
            int idx = tid + 256 * i;
            int r = idx >> 4, c = idx & 15;
            cpa16(sb + (unsigned)(2 * 32 * LDA * 4) + (unsigned)((0 * 32 + r) * LDB + c * 4) * 4,
                  W + (size_t)r * CC + n0 + c * 4);
        }
        CP_COMMIT();
    }

    for (int kt = 0; kt < 24; kt++) {
        if (kt < 23) {
            const int k0 = (kt + 1) * 32;
            const int buf = (kt + 1) & 1;
#pragma unroll
            for (int i = 0; i < 4; i++) {
                int idx = tid + 256 * i;
                int r = idx >> 5, c = idx & 31;
                cpa16(sb + (unsigned)((buf * 32 + r) * LDA + c * 4) * 4,
                      AT + (size_t)(k0 + r) * BT + m0 + c * 4);
            }
#pragma unroll
            for (int i = 0; i < 2; i++) {
                int idx = tid + 256 * i;
                int r = idx >> 4, c = idx & 15;
                cpa16(sb + (unsigned)(2 * 32 * LDA * 4) + (unsigned)((buf * 32 + r) * LDB + c * 4) * 4,
                      W + (size_t)(k0 + r) * CC + n0 + c * 4);
            }
            CP_COMMIT();
            CP_WAIT1();
        } else {
            CP_WAIT0();
        }
        __syncthreads();
        const int b = kt & 1;
#pragma unroll 16
        for (int kk = 0; kk < 32; kk++) KSTEP(S.As[b], S.Bs[b], kk)
        __syncthreads();
    }

    // ---- epilogue ----
#pragma unroll
    for (int p = 0; p < 4; p++) {
        float2 u[4];
#pragma unroll
        for (int j = 0; j < 4; j++) u[j] = up2(acc[j][p]);
        const int mlo = m0 + tm + 2 * p;
        if (z == 0) {
            *(float4*)&g_q[(size_t)mlo * CC + n0 + tn]       = make_float4(u[0].x, u[1].x, u[2].x, u[3].x);
            *(float4*)&g_q[(size_t)(mlo + 1) * CC + n0 + tn] = make_float4(u[0].y, u[1].y, u[2].y, u[3].y);
        } else if (z == 2) {
            *(float4*)&g_v[(size_t)mlo * CC + n0 + tn]       = make_float4(u[0].x, u[1].x, u[2].x, u[3].x);
            *(float4*)&g_v[(size_t)(mlo + 1) * CC + n0 + tn] = make_float4(u[0].y, u[1].y, u[2].y, u[3].y);
        }
        if (z == 0 || z == 1) {
            float* T = (z == 0) ? g_qT : g_kT;
            const int b2 = mlo >> 10, q = mlo & 1023;
#pragma unroll
            for (int j = 0; j < 4; j++) {
                const int n = n0 + tn + j;
                const int h = n >> 6, d = n & 63;
                *(float2*)&T[(size_t)((b2 * HH + h) * DD + d) * TT + q] =
                    make_float2(u[j].x, u[j].y);
            }
        }
    }
}

// =================================================================================
// relbias (validated)
// =================================================================================
__global__ void __launch_bounds__(64) relbias_kernel(const float* __restrict__ rph,
                                                     const float* __restrict__ rpw)
{
    const int bq = blockIdx.x;
    const int bh = bq >> 10;
    const int q  = bq & 1023;
    const int b = bh / HH, h = bh % HH;
    const int i = q >> 5, j = q & 31;
    const int t = threadIdx.x;

    __shared__ float qs[64];
    qs[t] = g_q[(size_t)(b * TT + q) * CC + h * DD + t];
    __syncthreads();

    if (t < 32) {
        const float* tab = rph + (size_t)(i - t + 31) * DD;
        float acc = 0.0f;
#pragma unroll
        for (int c = 0; c < DD; c++) acc = fmaf(qs[c], tab[c], acc);
        g_relh[(size_t)bq * 32 + t] = acc;
    } else {
        const int kw = t - 32;
        const float* tab = rpw + (size_t)(j - kw + 31) * DD;
        float acc = 0.0f;
#pragma unroll
        for (int c = 0; c < DD; c++) acc = fmaf(qs[c], tab[c], acc);
        g_relw[(size_t)bq * 32 + kw] = acc;
    }
}

// =================================================================================
// scores: S = Q K^T * SCALE + bias -> g_att; per-thread local online (m,l),
// merged across lanes once at the end. grid (8, 96), 256 thr.
// =================================================================================
__global__ void __launch_bounds__(256, 2) scores_gemm()
{
    extern __shared__ char smraw[];
    SmemS& S = *(SmemS*)smraw;
    const unsigned sb = s2u(smraw);
    const int z = blockIdx.y;
    const int m0 = blockIdx.x * 128;
    const int tid = threadIdx.x;
    const int tm = (tid >> 4) * 8, tn = (tid & 15) * 4;

    const unsigned off_K  = (unsigned)(64 * LDA * 4);
    const unsigned off_rh = off_K + (unsigned)(2 * 64 * LDB * 4);
    const unsigned off_rw = off_rh + 128 * 32 * 4;

    // ---- group 0: Q tile, rh, rw, K tile 0 ----
#pragma unroll
    for (int i = 0; i < 8; i++) {
        int idx = tid + 256 * i;
        int r = idx >> 5, c = idx & 31;
        cpa16(sb + (unsigned)(r * LDA + c * 4) * 4,
              g_qT + (size_t)(z * DD + r) * TT + m0 + c * 4);
    }
#pragma unroll
    for (int i = 0; i < 4; i++) {
        int idx = tid + 256 * i;
        int r = idx >> 3, c = idx & 7;
        cpa16(sb + off_rh + (unsigned)(r * 32 + c * 4) * 4,
              g_relh + (size_t)(z * TT + m0 + r) * 32 + c * 4);
        cpa16(sb + off_rw + (unsigned)(r * 32 + c * 4) * 4,
              g_relw + (size_t)(z * TT + m0 + r) * 32 + c * 4);
    }
#pragma unroll
    for (int i = 0; i < 4; i++) {
        int idx = tid + 256 * i;
        int r = idx >> 4, c = idx & 15;
        cpa16(sb + off_K + (unsigned)(r * LDB + c * 4) * 4,
              g_kT + (size_t)(z * DD + r) * TT + c * 4);
    }
    CP_COMMIT();

    float mloc[8], lloc[8];
#pragma unroll
    for (int r = 0; r < 8; r++) { mloc[r] = -INFINITY; lloc[r] = 0.0f; }

    const int khi_base = tn >> 5;
    const int tnm = tn & 31;

    for (int nt = 0; nt < 16; nt++) {
        if (nt < 15) {
            const int buf = (nt + 1) & 1;
#pragma unroll
            for (int i = 0; i < 4; i++) {
                int idx = tid + 256 * i;
                int r = idx >> 4, c = idx & 15;
                cpa16(sb + off_K + (unsigned)((buf * 64 + r) * LDB + c * 4) * 4,
                      g_kT + (size_t)(z * DD + r) * TT + (nt + 1) * 64 + c * 4);
            }
            CP_COMMIT();
            CP_WAIT1();
        } else {
            CP_WAIT0();
        }
        __syncthreads();

        ull acc[4][4];
#pragma unroll
        for (int j = 0; j < 4; j++)
#pragma unroll
            for (int p = 0; p < 4; p++) acc[j][p] = 0ull;

        const float (*Kc)[LDB] = S.Kt[nt & 1];
#pragma unroll 16
        for (int kk = 0; kk < 64; kk++) KSTEP(S.Qs, Kc, kk)

        // epilogue: bias, local online stats, store raw S
        const int khi = nt * 2 + khi_base;
#pragma unroll
        for (int p = 0; p < 4; p++) {
            float2 u[4];
#pragma unroll
            for (int j = 0; j < 4; j++) u[j] = up2(acc[j][p]);
#pragma unroll
            for (int half = 0; half < 2; half++) {
                const int r = 2 * p + half;
                const int rl = tm + r;
                const float bh = S.rh[rl][khi];
                float s0 = fmaf(half ? u[0].y : u[0].x, SCALE, bh + S.rw[rl][tnm]);
                float s1 = fmaf(half ? u[1].y : u[1].x, SCALE, bh + S.rw[rl][tnm + 1]);
                float s2 = fmaf(half ? u[2].y : u[2].x, SCALE, bh + S.rw[rl][tnm + 2]);
                float s3 = fmaf(half ? u[3].y : u[3].x, SCALE, bh + S.rw[rl][tnm + 3]);
                float tmax = fmaxf(fmaxf(s0, s1), fmaxf(s2, s3));
                const float mn = fmaxf(mloc[r], tmax);
                lloc[r] = lloc[r] * __expf(mloc[r] - mn)
                        + __expf(s0 - mn) + __expf(s1 - mn)
                        + __expf(s2 - mn) + __expf(s3 - mn);
                mloc[r] = mn;
                *(float4*)&g_att[((size_t)z * TT + m0 + rl) * TT + nt * 64 + tn] =
                    make_float4(s0, s1, s2, s3);
            }
        }
        __syncthreads();
    }

    // ---- merge (m,l) across the 16 lanes of each row group ----
#pragma unroll
    for (int r = 0; r < 8; r++) {
        float mm = mloc[r], ll = lloc[r];
#pragma unroll
        for (int off = 1; off < 16; off <<= 1) {
            float mo  = __shfl_xor_sync(0xffffffffu, mm, off);
            float lo_ = __shfl_xor_sync(0xffffffffu, ll, off);
            float mn = fmaxf(mm, mo);
            ll = ll * __expf(mm - mn) + lo_ * __expf(mo - mn);
            mm = mn;
        }
        if ((tid & 15) == 0) {
            g_m[z * TT + m0 + tm + r] = mm;
            g_l[z * TT + m0 + tm + r] = ll;
        }
    }
}

// =================================================================================
// pv: oT = (softmax(S) @ V)^T. A staged w/ expf; B via cp.async. grid (8, 96).
// =================================================================================
__global__ void __launch_bounds__(256, 2) pv_gemm()
{
    extern __shared__ char smraw[];
    SmemG& S = *(SmemG*)smraw;
    const unsigned sb = s2u(smraw);
    const int z = blockIdx.y, b = z / HH, h = z % HH;
    const int m0 = blockIdx.x * 128;
    const int tid = threadIdx.x;
    const int tm = (tid >> 4) * 8, tn = (tid & 15) * 4;
    const int ar = tid >> 3, akq = (tid & 7) * 4;
    const unsigned off_B = (unsigned)(2 * 32 * LDA * 4);

    const float* att = g_att + ((size_t)z * TT + m0) * TT;
    const float* vb  = g_v + (size_t)(b * TT) * CC + h * DD;

    float mrow[4];
#pragma unroll
    for (int i = 0; i < 4; i++) mrow[i] = g_m[z * TT + m0 + ar + 32 * i];

    ull acc[4][4];
#pragma unroll
    for (int j = 0; j < 4; j++)
#pragma unroll
        for (int p = 0; p < 4; p++) acc[j][p] = 0ull;

    // prologue: B0 via cp.async; A0 staged+exp
    {
#pragma unroll
        for (int i = 0; i < 2; i++) {
            int idx = tid + 256 * i;
            int r = idx >> 4, c = idx & 15;
            cpa16(sb + off_B + (unsigned)(r * LDB + c * 4) * 4,
                  vb + (size_t)r * CC + c * 4);
        }
        CP_COMMIT();
#pragma unroll
        for (int i = 0; i < 4; i++) {
            float4 v = *(const float4*)&att[(size_t)(ar + 32 * i) * TT + akq];
            S.As[0][akq + 0][ar + 32 * i] = __expf(v.x - mrow[i]);
            S.As[0][akq + 1][ar + 32 * i] = __expf(v.y - mrow[i]);
            S.As[0][akq + 2][ar + 32 * i] = __expf(v.z - mrow[i]);
            S.As[0][akq + 3][ar + 32 * i] = __expf(v.w - mrow[i]);
        }
    }

    float4 fa[4];
    for (int kt = 0; kt < 32; kt++) {
        if (kt < 31) {
            const int k0 = (kt + 1) * 32;
            const int buf = (kt + 1) & 1;
#pragma unroll
            for (int i = 0; i < 2; i++) {
                int idx = tid + 256 * i;
                int r = idx >> 4, c = idx & 15;
                cpa16(sb + off_B + (unsigned)((buf * 32 + r) * LDB + c * 4) * 4,
                      vb + (size_t)(k0 + r) * CC + c * 4);
            }
            CP_COMMIT();
#pragma unroll
            for (int i = 0; i < 4; i++)
                fa[i] = *(const float4*)&att[(size_t)(ar + 32 * i) * TT + k0 + akq];
            CP_WAIT1();
        } else {
            CP_WAIT0();
        }
        __syncthreads();
        const int bf = kt & 1;
#pragma unroll 16
        for (int kk = 0; kk < 32; kk++) KSTEP(S.As[bf], S.Bs[bf], kk)
        __syncthreads();
        if (kt < 31) {
            const int nb = (kt + 1) & 1;
#pragma unroll
            for (int i = 0; i < 4; i++) {
                S.As[nb][akq + 0][ar + 32 * i] = __expf(fa[i].x - mrow[i]);
                S.As[nb][akq + 1][ar + 32 * i] = __expf(fa[i].y - mrow[i]);
                S.As[nb][akq + 2][ar + 32 * i] = __expf(fa[i].z - mrow[i]);
                S.As[nb][akq + 3][ar + 32 * i] = __expf(fa[i].w - mrow[i]);
            }
        }
    }

    // epilogue -> g_oT [c][m], scaled by 1/l
#pragma unroll
    for (int p = 0; p < 4; p++) {
        const int mlo = m0 + tm + 2 * p;
        const float i0 = 1.0f / g_l[z * TT + mlo];
        const float i1 = 1.0f / g_l[z * TT + mlo + 1];
#pragma unroll
        for (int j = 0; j < 4; j++) {
            float2 u = up2(acc[j][p]);
            const int c = h * DD + tn + j;
            *(float2*)&g_oT[(size_t)c * BT + b * TT + mlo] =
                make_float2(u.x * i0, u.y * i1);
        }
    }
}

// =================================================================================
// out: out = oT^T @ Wo + bo. grid (12, 64), same skeleton as qkv.
// =================================================================================
__global__ void __launch_bounds__(256, 3) out_gemm(const float* __restrict__ Wo,
                                                   const float* __restrict__ bo,
                                                   float* __restrict__ Out)
{
    extern __shared__ char smraw[];
    SmemG& S = *(SmemG*)smraw;
    const unsigned sb = s2u(smraw);
    const int tid = threadIdx.x;
    const int n0 = blockIdx.x * 64, m0 = blockIdx.y * 128;
    const int tm = (tid >> 4) * 8, tn = (tid & 15) * 4;
    const unsigned off_B = (unsigned)(2 * 32 * LDA * 4);

    ull acc[4][4];
#pragma unroll
    for (int j = 0; j < 4; j++)
#pragma unroll
        for (int p = 0; p < 4; p++) acc[j][p] = 0ull;

    {
#pragma unroll
        for (int i = 0; i < 4; i++) {
            int idx = tid + 256 * i;
            int r = idx >> 5, c = idx & 31;
            cpa16(sb + (unsigned)(r * LDA + c * 4) * 4,
                  g_oT + (size_t)r * BT + m0 + c * 4);
        }
#pragma unroll
        for (int i = 0; i < 2; i++) {
            int idx = tid + 256 * i;
            int r = idx >> 4, c = idx & 15;
            cpa16(sb + off_B + (unsigned)(r * LDB + c * 4) * 4,
                  Wo + (size_t)r * CC + n0 + c * 4);
        }
        CP_COMMIT();
    }

    for (int kt = 0; kt < 24; kt++) {
        if (kt < 23) {
            const int k0 = (kt + 1) * 32;
            const int buf = (kt + 1) & 1;
#pragma unroll
            for (int i = 0; i < 4; i++) {
                int idx = tid + 256 * i;
                int r = idx >> 5, c = idx & 31;
                cpa16(sb + (unsigned)((buf * 32 + r) * LDA + c * 4) * 4,
                      g_oT + (size_t)(k0 + r) * BT + m0 + c * 4);
            }
#pragma unroll
            for (int i = 0; i < 2; i++) {
                int idx = tid + 256 * i;
                int r = idx >> 4, c = idx & 15;
                cpa16(sb + off_B + (unsigned)((buf * 32 + r) * LDB + c * 4) * 4,
                      Wo + (size_t)(k0 + r) * CC + n0 + c * 4);
            }
            CP_COMMIT();
            CP_WAIT1();
        } else {
            CP_WAIT0();
        }
        __syncthreads();
        const int b = kt & 1;
#pragma unroll 16
        for (int kk = 0; kk < 32; kk++) KSTEP(S.As[b], S.Bs[b], kk)
        __syncthreads();
    }

    const float4 bv = *(const float4*)&bo[n0 + tn];
#pragma unroll
    for (int p = 0; p < 4; p++) {
        float2 u[4];
#pragma unroll
        for (int j = 0; j < 4; j++) u[j] = up2(acc[j][p]);
        const int mlo = m0 + tm + 2 * p;
        *(float4*)&Out[(size_t)mlo * CC + n0 + tn] =
            make_float4(u[0].x + bv.x, u[1].x + bv.y, u[2].x + bv.z, u[3].x + bv.w);
        *(float4*)&Out[(size_t)(mlo + 1) * CC + n0 + tn] =
            make_float4(u[0].y + bv.x, u[1].y + bv.y, u[2].y + bv.z, u[3].y + bv.w);
    }
}

// =================================================================================
extern "C" void kernel_launch(void* const* d_in, const int* in_sizes, int n_in,
                              void* d_out, int out_size)
{
    const float* x   = (const float*)d_in[0];
    const float* ctx = (const float*)d_in[1];
    const float* Wq  = (const float*)d_in[2];
    const float* Wk  = (const float*)d_in[3];
    const float* Wv  = (const float*)d_in[4];
    const float* Wo  = (const float*)d_in[5];
    const float* bo  = (const float*)d_in[6];
    const float* rph = (const float*)d_in[7];
    const float* rpw = (const float*)d_in[8];
    float* out = (float*)d_out;

    cudaFuncSetAttribute(qkv_gemm,    cudaFuncAttributeMaxDynamicSharedMemorySize, (int)sizeof(SmemG));
    cudaFuncSetAttribute(out_gemm,    cudaFuncAttributeMaxDynamicSharedMemorySize, (int)sizeof(SmemG));
    cudaFuncSetAttribute(pv_gemm,     cudaFuncAttributeMaxDynamicSharedMemorySize, (int)sizeof(SmemG));
    cudaFuncSetAttribute(scores_gemm, cudaFuncAttributeMaxDynamicSharedMemorySize, (int)sizeof(SmemS));

    transpose_in<<<dim3(256, 24, 2), dim3(32, 8)>>>(x, ctx);
    qkv_gemm<<<dim3(12, 64, 3), 256, sizeof(SmemG)>>>(Wq, Wk, Wv);
    relbias_kernel<<<BH * TT, 64>>>(rph, rpw);
    scores_gemm<<<dim3(8, 96), 256, sizeof(SmemS)>>>();
    pv_gemm<<<dim3(8, 96), 256, sizeof(SmemG)>>>();
    out_gemm<<<dim3(12, 64), 256, sizeof(SmemG)>>>(Wo, bo, out);
}

// round 8
// speedup vs baseline: 1.2764x; 1.0018x over previous
#include <cuda_runtime.h>
#include <math.h>

#define BB 8
#define TT 1024
#define CC 768
#define HH 12
#define DD 64
#define BH (BB*HH)          // 96
#define BT (BB*TT)          // 8192
#define SCALE 0.125f

// ---------------- scratch (device globals; no allocation allowed) ----------------
__device__ float g_xT[CC*BT];                    // x transposed   [c][m]
__device__ float g_cT[CC*BT];                    // ctx transposed [c][m]
__device__ float g_q [BT*CC];                    // q natural (relbias)
__device__ float g_qT[BH*DD*TT];                 // q  [bh][d][q]
__device__ float g_kT[BH*DD*TT];                 // k  [bh][d][key]
__device__ float g_v [BT*CC];                    // v natural (pv B)
__device__ float g_oT[CC*BT];                    // attention out transposed [c][m]
__device__ float g_relh[BH*TT*32];
__device__ float g_relw[BH*TT*32];
__device__ float g_att[(size_t)BH*TT*TT];        // raw biased scores
__device__ float g_m[BH*TT];
__device__ float g_l[BH*TT];

// ---------------- packed fp32x2 + async helpers ----------------------------------
typedef unsigned long long ull;
__device__ __forceinline__ ull bc2(float v) {
    ull r; asm("mov.b64 %0, {%1, %1};" : "=l"(r) : "f"(v)); return r;
}
__device__ __forceinline__ void ffma2(ull& d, ull a, ull b) {
    asm("fma.rn.f32x2 %0, %1, %2, %0;" : "+l"(d) : "l"(a), "l"(b));
}
__device__ __forceinline__ float2 up2(ull v) {
    float2 f; asm("mov.b64 {%0, %1}, %2;" : "=f"(f.x), "=f"(f.y) : "l"(v)); return f;
}
__device__ __forceinline__ unsigned s2u(const void* p) {
    unsigned a;
    asm("{ .reg .u64 t; cvta.to.shared.u64 t, %1; cvt.u32.u64 %0, t; }" : "=r"(a) : "l"(p));
    return a;
}
__device__ __forceinline__ void cpa16(unsigned dst, const float* src) {
    asm volatile("cp.async.cg.shared.global [%0], [%1], 16;" :: "r"(dst), "l"(src) : "memory");
}
#define CP_COMMIT() asm volatile("cp.async.commit_group;" ::: "memory")
#define CP_WAIT0()  asm volatile("cp.async.wait_group 0;" ::: "memory")
#define CP_WAIT1()  asm volatile("cp.async.wait_group 1;" ::: "memory")

#define LDA 132      // floats, [k][m] tile stride (m=128)
#define LDB 68       // floats, [k][n] tile stride (n=64)

struct SmemG { float As[2][32][LDA]; float Bs[2][32][LDB]; };        // 51200 B
struct SmemS {                                                        // 101376 B
    float Qs[64][LDA];
    float Kt[2][64][LDB];
    float rh[128][32];
    float rw[128][32];
};

// one k-step batch: acc[nj][mpair]  (16 FFMA2, 3 LDS.128, 4 MOV)
#define KSTEP(AS, BS, kk)                                              \
    {                                                                  \
        ulonglong2 a01 = *(const ulonglong2*)&(AS)[kk][tm];            \
        ulonglong2 a23 = *(const ulonglong2*)&(AS)[kk][tm + 4];        \
        float4 bv = *(const float4*)&(BS)[kk][tn];                     \
        ull b0 = bc2(bv.x), b1 = bc2(bv.y), b2 = bc2(bv.z), b3 = bc2(bv.w); \
        ffma2(acc[0][0], a01.x, b0); ffma2(acc[0][1], a01.y, b0);      \
        ffma2(acc[0][2], a23.x, b0); ffma2(acc[0][3], a23.y, b0);      \
        ffma2(acc[1][0], a01.x, b1); ffma2(acc[1][1], a01.y, b1);      \
        ffma2(acc[1][2], a23.x, b1); ffma2(acc[1][3], a23.y, b1);      \
        ffma2(acc[2][0], a01.x, b2); ffma2(acc[2][1], a01.y, b2);      \
        ffma2(acc[2][2], a23.x, b2); ffma2(acc[2][3], a23.y, b2);      \
        ffma2(acc[3][0], a01.x, b3); ffma2(acc[3][1], a01.y, b3);      \
        ffma2(acc[3][2], a23.x, b3); ffma2(acc[3][3], a23.y, b3);      \
    }

// =================================================================================
// transpose_in: xT/cT [c][m] from x/ctx [m][c]. grid (256, 24, 2), block (32,8).
// =================================================================================
__global__ void __launch_bounds__(256) transpose_in(const float* __restrict__ x,
                                                    const float* __restrict__ ctx)
{
    __shared__ float t[32][33];
    const float* src = blockIdx.z ? ctx : x;
    float* dst = blockIdx.z ? g_cT : g_xT;
    const int m0 = blockIdx.x * 32, c0 = blockIdx.y * 32;
    const int tx = threadIdx.x, ty = threadIdx.y;
#pragma unroll
    for (int i = 0; i < 4; i++)
        t[ty + 8 * i][tx] = src[(size_t)(m0 + ty + 8 * i) * CC + c0 + tx];
    __syncthreads();
#pragma unroll
    for (int i = 0; i < 4; i++)
        dst[(size_t)(c0 + ty + 8 * i) * BT + m0 + tx] = t[tx][ty + 8 * i];
}

// =================================================================================
// qkv: {q, k, v} = {xT,cT,cT}^T @ W.  Tile 128x64, BK=32, cp.async pipeline.
// grid (12, 64, 3), 256 thr. NOTE: minBlocks=2 (3 caused 85-reg cap -> spills).
// =================================================================================
__global__ void __launch_bounds__(256, 2) qkv_gemm(const float* __restrict__ Wq,
                                                   const float* __restrict__ Wk,
                                                   const float* __restrict__ Wv)
{
    extern __shared__ char smraw[];
    SmemG& S = *(SmemG*)smraw;
    const unsigned sb = s2u(smraw);
    const int z = blockIdx.z;
    const float* AT = (z == 0) ? g_xT : g_cT;
    const float* W  = (z == 0) ? Wq : (z == 1 ? Wk : Wv);

    const int tid = threadIdx.x;
    const int n0 = blockIdx.x * 64, m0 = blockIdx.y * 128;
    const int tm = (tid >> 4) * 8, tn = (tid & 15) * 4;

    ull acc[4][4];
#pragma unroll
    for (int j = 0; j < 4; j++)
#pragma unroll
        for (int p = 0; p < 4; p++) acc[j][p] = 0ull;

    {
#pragma unroll
        for (int i = 0; i < 4; i++) {
            int idx = tid + 256 * i;
            int r = idx >> 5, c = idx & 31;
            cpa16(sb + (unsigned)(r * LDA + c * 4) * 4,
                  AT + (size_t)r * BT + m0 + c * 4);
        }
#pragma unroll
        for (int i = 0; i < 2; i++) {
            int idx = tid + 256 * i;
            int r = idx >> 4, c = idx & 15;
            cpa16(sb + (unsigned)(2 * 32 * LDA * 4) + (unsigned)((0 * 32 + r) * LDB + c * 4) * 4,
                  W + (size_t)r * CC + n0 + c * 4);
        }
        CP_COMMIT();
    }

    for (int kt = 0; kt < 24; kt++) {
        if (kt < 23) {
            const int k0 = (kt + 1) * 32;
            const int buf = (kt + 1) & 1;
#pragma unroll
            for (int i = 0; i < 4; i++) {
                int idx = tid + 256 * i;
                int r = idx >> 5, c = idx & 31;
                cpa16(sb + (unsigned)((buf * 32 + r) * LDA + c * 4) * 4,
                      AT + (size_t)(k0 + r) * BT + m0 + c * 4);
            }
#pragma unroll
            for (int i = 0; i < 2; i++) {
                int idx = tid + 256 * i;
                int r = idx >> 4, c = idx & 15;
                cpa16(sb + (unsigned)(2 * 32 * LDA * 4) + (unsigned)((buf * 32 + r) * LDB + c * 4) * 4,
                      W + (size_t)(k0 + r) * CC + n0 + c * 4);
            }
            CP_COMMIT();
            CP_WAIT1();
        } else {
            CP_WAIT0();
        }
        __syncthreads();
        const int b = kt & 1;
#pragma unroll 16
        for (int kk = 0; kk < 32; kk++) KSTEP(S.As[b], S.Bs[b], kk)
        __syncthreads();
    }

    // ---- epilogue: natural writes (q, v) direct; transposed (q, k) via smem ----
#pragma unroll
    for (int p = 0; p < 4; p++) {
        float2 u[4];
#pragma unroll
        for (int j = 0; j < 4; j++) u[j] = up2(acc[j][p]);
        const int mlo = m0 + tm + 2 * p;
        if (z == 0) {
            *(float4*)&g_q[(size_t)mlo * CC + n0 + tn]       = make_float4(u[0].x, u[1].x, u[2].x, u[3].x);
            *(float4*)&g_q[(size_t)(mlo + 1) * CC + n0 + tn] = make_float4(u[0].y, u[1].y, u[2].y, u[3].y);
        } else if (z == 2) {
            *(float4*)&g_v[(size_t)mlo * CC + n0 + tn]       = make_float4(u[0].x, u[1].x, u[2].x, u[3].x);
            *(float4*)&g_v[(size_t)(mlo + 1) * CC + n0 + tn] = make_float4(u[0].y, u[1].y, u[2].y, u[3].y);
        }
    }
    if (z <= 1) {
        float* T = (float*)smraw;            // 64 x LDA staging (fits in As)
#pragma unroll
        for (int p = 0; p < 4; p++) {
#pragma unroll
            for (int j = 0; j < 4; j++) {
                float2 u = up2(acc[j][p]);
                T[(tn + j) * LDA + tm + 2 * p]     = u.x;
                T[(tn + j) * LDA + tm + 2 * p + 1] = u.y;
            }
        }
        __syncthreads();
        float* Tt = (z == 0) ? g_qT : g_kT;
        const int b2 = m0 >> 10, qb = m0 & 1023;
#pragma unroll
        for (int i = 0; i < 8; i++) {
            int idx = tid + 256 * i;             // 2048 float4
            int r = idx >> 5, c4 = (idx & 31) * 4;
            const int n = n0 + r, h = n >> 6, d = n & 63;
            *(float4*)&Tt[(size_t)((b2 * HH + h) * DD + d) * TT + qb + c4] =
                *(const float4*)&T[r * LDA + c4];
        }
    }
}

// =================================================================================
// relbias (validated)
// =================================================================================
__global__ void __launch_bounds__(64) relbias_kernel(const float* __restrict__ rph,
                                                     const float* __restrict__ rpw)
{
    const int bq = blockIdx.x;
    const int bh = bq >> 10;
    const int q  = bq & 1023;
    const int b = bh / HH, h = bh % HH;
    const int i = q >> 5, j = q & 31;
    const int t = threadIdx.x;

    __shared__ float qs[64];
    qs[t] = g_q[(size_t)(b * TT + q) * CC + h * DD + t];
    __syncthreads();

    if (t < 32) {
        const float* tab = rph + (size_t)(i - t + 31) * DD;
        float acc = 0.0f;
#pragma unroll
        for (int c = 0; c < DD; c++) acc = fmaf(qs[c], tab[c], acc);
        g_relh[(size_t)bq * 32 + t] = acc;
    } else {
        const int kw = t - 32;
        const float* tab = rpw + (size_t)(j - kw + 31) * DD;
        float acc = 0.0f;
#pragma unroll
        for (int c = 0; c < DD; c++) acc = fmaf(qs[c], tab[c], acc);
        g_relw[(size_t)bq * 32 + kw] = acc;
    }
}

// =================================================================================
// scores: S = Q K^T * SCALE + bias -> g_att; per-thread local online (m,l),
// merged across lanes once at the end. grid (8, 96), 256 thr.
// =================================================================================
__global__ void __launch_bounds__(256, 2) scores_gemm()
{
    extern __shared__ char smraw[];
    SmemS& S = *(SmemS*)smraw;
    const unsigned sb = s2u(smraw);
    const int z = blockIdx.y;
    const int m0 = blockIdx.x * 128;
    const int tid = threadIdx.x;
    const int tm = (tid >> 4) * 8, tn = (tid & 15) * 4;

    const unsigned off_K  = (unsigned)(64 * LDA * 4);
    const unsigned off_rh = off_K + (unsigned)(2 * 64 * LDB * 4);
    const unsigned off_rw = off_rh + 128 * 32 * 4;

#pragma unroll
    for (int i = 0; i < 8; i++) {
        int idx = tid + 256 * i;
        int r = idx >> 5, c = idx & 31;
        cpa16(sb + (unsigned)(r * LDA + c * 4) * 4,
              g_qT + (size_t)(z * DD + r) * TT + m0 + c * 4);
    }
#pragma unroll
    for (int i = 0; i < 4; i++) {
        int idx = tid + 256 * i;
        int r = idx >> 3, c = idx & 7;
        cpa16(sb + off_rh + (unsigned)(r * 32 + c * 4) * 4,
              g_relh + (size_t)(z * TT + m0 + r) * 32 + c * 4);
        cpa16(sb + off_rw + (unsigned)(r * 32 + c * 4) * 4,
              g_relw + (size_t)(z * TT + m0 + r) * 32 + c * 4);
    }
#pragma unroll
    for (int i = 0; i < 4; i++) {
        int idx = tid + 256 * i;
        int r = idx >> 4, c = idx & 15;
        cpa16(sb + off_K + (unsigned)(r * LDB + c * 4) * 4,
              g_kT + (size_t)(z * DD + r) * TT + c * 4);
    }
    CP_COMMIT();

    float mloc[8], lloc[8];
#pragma unroll
    for (int r = 0; r < 8; r++) { mloc[r] = -INFINITY; lloc[r] = 0.0f; }

    const int khi_base = tn >> 5;
    const int tnm = tn & 31;

    for (int nt = 0; nt < 16; nt++) {
        if (nt < 15) {
            const int buf = (nt + 1) & 1;
#pragma unroll
            for (int i = 0; i < 4; i++) {
                int idx = tid + 256 * i;
                int r = idx >> 4, c = idx & 15;
                cpa16(sb + off_K + (unsigned)((buf * 64 + r) * LDB + c * 4) * 4,
                      g_kT + (size_t)(z * DD + r) * TT + (nt + 1) * 64 + c * 4);
            }
            CP_COMMIT();
            CP_WAIT1();
        } else {
            CP_WAIT0();
        }
        __syncthreads();

        ull acc[4][4];
#pragma unroll
        for (int j = 0; j < 4; j++)
#pragma unroll
            for (int p = 0; p < 4; p++) acc[j][p] = 0ull;

        const float (*Kc)[LDB] = S.Kt[nt & 1];
#pragma unroll 16
        for (int kk = 0; kk < 64; kk++) KSTEP(S.Qs, Kc, kk)

        const int khi = nt * 2 + khi_base;
#pragma unroll
        for (int p = 0; p < 4; p++) {
            float2 u[4];
#pragma unroll
            for (int j = 0; j < 4; j++) u[j] = up2(acc[j][p]);
#pragma unroll
            for (int half = 0; half < 2; half++) {
                const int r = 2 * p + half;
                const int rl = tm + r;
                const float bh = S.rh[rl][khi];
                float s0 = fmaf(half ? u[0].y : u[0].x, SCALE, bh + S.rw[rl][tnm]);
                float s1 = fmaf(half ? u[1].y : u[1].x, SCALE, bh + S.rw[rl][tnm + 1]);
                float s2 = fmaf(half ? u[2].y : u[2].x, SCALE, bh + S.rw[rl][tnm + 2]);
                float s3 = fmaf(half ? u[3].y : u[3].x, SCALE, bh + S.rw[rl][tnm + 3]);
                float tmax = fmaxf(fmaxf(s0, s1), fmaxf(s2, s3));
                const float mn = fmaxf(mloc[r], tmax);
                lloc[r] = lloc[r] * __expf(mloc[r] - mn)
                        + __expf(s0 - mn) + __expf(s1 - mn)
                        + __expf(s2 - mn) + __expf(s3 - mn);
                mloc[r] = mn;
                *(float4*)&g_att[((size_t)z * TT + m0 + rl) * TT + nt * 64 + tn] =
                    make_float4(s0, s1, s2, s3);
            }
        }
        __syncthreads();
    }

#pragma unroll
    for (int r = 0; r < 8; r++) {
        float mm = mloc[r], ll = lloc[r];
#pragma unroll
        for (int off = 1; off < 16; off <<= 1) {
            float mo  = __shfl_xor_sync(0xffffffffu, mm, off);
            float lo_ = __shfl_xor_sync(0xffffffffu, ll, off);
            float mn = fmaxf(mm, mo);
            ll = ll * __expf(mm - mn) + lo_ * __expf(mo - mn);
            mm = mn;
        }
        if ((tid & 15) == 0) {
            g_m[z * TT + m0 + tm + r] = mm;
            g_l[z * TT + m0 + tm + r] = ll;
        }
    }
}

// =================================================================================
// pv: oT = (softmax(S) @ V)^T. A staged w/ expf; B via cp.async. grid (8, 96).
// =================================================================================
__global__ void __launch_bounds__(256, 2) pv_gemm()
{
    extern __shared__ char smraw[];
    SmemG& S = *(SmemG*)smraw;
    const unsigned sb = s2u(smraw);
    const int z = blockIdx.y, b = z / HH, h = z % HH;
    const int m0 = blockIdx.x * 128;
    const int tid = threadIdx.x;
    const int tm = (tid >> 4) * 8, tn = (tid & 15) * 4;
    const int ar = tid >> 3, akq = (tid & 7) * 4;
    const unsigned off_B = (unsigned)(2 * 32 * LDA * 4);

    const float* att = g_att + ((size_t)z * TT + m0) * TT;
    const float* vb  = g_v + (size_t)(b * TT) * CC + h * DD;

    float mrow[4];
#pragma unroll
    for (int i = 0; i < 4; i++) mrow[i] = g_m[z * TT + m0 + ar + 32 * i];

    ull acc[4][4];
#pragma unroll
    for (int j = 0; j < 4; j++)
#pragma unroll
        for (int p = 0; p < 4; p++) acc[j][p] = 0ull;

    {
#pragma unroll
        for (int i = 0; i < 2; i++) {
            int idx = tid + 256 * i;
            int r = idx >> 4, c = idx & 15;
            cpa16(sb + off_B + (unsigned)(r * LDB + c * 4) * 4,
                  vb + (size_t)r * CC + c * 4);
        }
        CP_COMMIT();
#pragma unroll
        for (int i = 0; i < 4; i++) {
            float4 v = *(const float4*)&att[(size_t)(ar + 32 * i) * TT + akq];
            S.As[0][akq + 0][ar + 32 * i] = __expf(v.x - mrow[i]);
            S.As[0][akq + 1][ar + 32 * i] = __expf(v.y - mrow[i]);
            S.As[0][akq + 2][ar + 32 * i] = __expf(v.z - mrow[i]);
            S.As[0][akq + 3][ar + 32 * i] = __expf(v.w - mrow[i]);
        }
    }

    float4 fa[4];
    for (int kt = 0; kt < 32; kt++) {
        if (kt < 31) {
            const int k0 = (kt + 1) * 32;
            const int buf = (kt + 1) & 1;
#pragma unroll
            for (int i = 0; i < 2; i++) {
                int idx = tid + 256 * i;
                int r = idx >> 4, c = idx & 15;
                cpa16(sb + off_B + (unsigned)((buf * 32 + r) * LDB + c * 4) * 4,
                      vb + (size_t)(k0 + r) * CC + c * 4);
            }
            CP_COMMIT();
#pragma unroll
            for (int i = 0; i < 4; i++)
                fa[i] = *(const float4*)&att[(size_t)(ar + 32 * i) * TT + k0 + akq];
            CP_WAIT1();
        } else {
            CP_WAIT0();
        }
        __syncthreads();
        const int bf = kt & 1;
#pragma unroll 16
        for (int kk = 0; kk < 32; kk++) KSTEP(S.As[bf], S.Bs[bf], kk)
        __syncthreads();
        if (kt < 31) {
            const int nb = (kt + 1) & 1;
#pragma unroll
            for (int i = 0; i < 4; i++) {
                S.As[nb][akq + 0][ar + 32 * i] = __expf(fa[i].x - mrow[i]);
                S.As[nb][akq + 1][ar + 32 * i] = __expf(fa[i].y - mrow[i]);
                S.As[nb][akq + 2][ar + 32 * i] = __expf(fa[i].z - mrow[i]);
                S.As[nb][akq + 3][ar + 32 * i] = __expf(fa[i].w - mrow[i]);
            }
        }
    }

    // ---- epilogue: stage through smem, write g_oT coalesced ----
    __syncthreads();
    float* T = (float*)smraw;                // 64 x LDA staging
#pragma unroll
    for (int p = 0; p < 4; p++) {
        const int mlo = m0 + tm + 2 * p;
        const float i0 = 1.0f / g_l[z * TT + mlo];
        const float i1 = 1.0f / g_l[z * TT + mlo + 1];
#pragma unroll
        for (int j = 0; j < 4; j++) {
            float2 u = up2(acc[j][p]);
            T[(tn + j) * LDA + tm + 2 * p]     = u.x * i0;
            T[(tn + j) * LDA + tm + 2 * p + 1] = u.y * i1;
        }
    }
    __syncthreads();
#pragma unroll
    for (int i = 0; i < 8; i++) {
        int idx = tid + 256 * i;                 // 2048 float4
        int r = idx >> 5, c4 = (idx & 31) * 4;
        *(float4*)&g_oT[(size_t)(h * DD + r) * BT + b * TT + m0 + c4] =
            *(const float4*)&T[r * LDA + c4];
    }
}

// =================================================================================
// out: out = oT^T @ Wo + bo. grid (12, 64). minBlocks=2 (3 caused spills).
// =================================================================================
__global__ void __launch_bounds__(256, 2) out_gemm(const float* __restrict__ Wo,
                                                   const float* __restrict__ bo,
                                                   float* __restrict__ Out)
{
    extern __shared__ char smraw[];
    SmemG& S = *(SmemG*)smraw;
    const unsigned sb = s2u(smraw);
    const int tid = threadIdx.x;
    const int n0 = blockIdx.x * 64, m0 = blockIdx.y * 128;
    const int tm = (tid >> 4) * 8, tn = (tid & 15) * 4;
    const unsigned off_B = (unsigned)(2 * 32 * LDA * 4);

    ull acc[4][4];
#pragma unroll
    for (int j = 0; j < 4; j++)
#pragma unroll
        for (int p = 0; p < 4; p++) acc[j][p] = 0ull;

    {
#pragma unroll
        for (int i = 0; i < 4; i++) {
            int idx = tid + 256 * i;
            int r = idx >> 5, c = idx & 31;
            cpa16(sb + (unsigned)(r * LDA + c * 4) * 4,
                  g_oT + (size_t)r * BT + m0 + c * 4);
        }
#pragma unroll
        for (int i = 0; i < 2; i++) {
            int idx = tid + 256 * i;
            int r = idx >> 4, c = idx & 15;
            cpa16(sb + off_B + (unsigned)(r * LDB + c * 4) * 4,
                  Wo + (size_t)r * CC + n0 + c * 4);
        }
        CP_COMMIT();
    }

    for (int kt = 0; kt < 24; kt++) {
        if (kt < 23) {
            const int k0 = (kt + 1) * 32;
            const int buf = (kt + 1) & 1;
#pragma unroll
            for (int i = 0; i < 4; i++) {
                int idx = tid + 256 * i;
                int r = idx >> 5, c = idx & 31;
                cpa16(sb + (unsigned)((buf * 32 + r) * LDA + c * 4) * 4,
                      g_oT + (size_t)(k0 + r) * BT + m0 + c * 4);
            }
#pragma unroll
            for (int i = 0; i < 2; i++) {
                int idx = tid + 256 * i;
                int r = idx >> 4, c = idx & 15;
                cpa16(sb + off_B + (unsigned)((buf * 32 + r) * LDB + c * 4) * 4,
                      Wo + (size_t)(k0 + r) * CC + n0 + c * 4);
            }
            CP_COMMIT();
            CP_WAIT1();
        } else {
            CP_WAIT0();
        }
        __syncthreads();
        const int b = kt & 1;
#pragma unroll 16
        for (int kk = 0; kk < 32; kk++) KSTEP(S.As[b], S.Bs[b], kk)
        __syncthreads();
    }

    const float4 bv = *(const float4*)&bo[n0 + tn];
#pragma unroll
    for (int p = 0; p < 4; p++) {
        float2 u[4];
#pragma unroll
        for (int j = 0; j < 4; j++) u[j] = up2(acc[j][p]);
        const int mlo = m0 + tm + 2 * p;
        *(float4*)&Out[(size_t)mlo * CC + n0 + tn] =
            make_float4(u[0].x + bv.x, u[1].x + bv.y, u[2].x + bv.z, u[3].x + bv.w);
        *(float4*)&Out[(size_t)(mlo + 1) * CC + n0 + tn] =
            make_float4(u[0].y + bv.x, u[1].y + bv.y, u[2].y + bv.z, u[3].y + bv.w);
    }
}

// =================================================================================
extern "C" void kernel_launch(void* const* d_in, const int* in_sizes, int n_in,
                              void* d_out, int out_size)
{
    const float* x   = (const float*)d_in[0];
    const float* ctx = (const float*)d_in[1];
    const float* Wq  = (const float*)d_in[2];
    const float* Wk  = (const float*)d_in[3];
    const float* Wv  = (const float*)d_in[4];
    const float* Wo  = (const float*)d_in[5];
    const float* bo  = (const float*)d_in[6];
    const float* rph = (const float*)d_in[7];
    const float* rpw = (const float*)d_in[8];
    float* out = (float*)d_out;

    cudaFuncSetAttribute(qkv_gemm,    cudaFuncAttributeMaxDynamicSharedMemorySize, (int)sizeof(SmemG));
    cudaFuncSetAttribute(out_gemm,    cudaFuncAttributeMaxDynamicSharedMemorySize, (int)sizeof(SmemG));
    cudaFuncSetAttribute(pv_gemm,     cudaFuncAttributeMaxDynamicSharedMemorySize, (int)sizeof(SmemG));
    cudaFuncSetAttribute(scores_gemm, cudaFuncAttributeMaxDynamicSharedMemorySize, (int)sizeof(SmemS));

    transpose_in<<<dim3(256, 24, 2), dim3(32, 8)>>>(x, ctx);
    qkv_gemm<<<dim3(12, 64, 3), 256, sizeof(SmemG)>>>(Wq, Wk, Wv);
    relbias_kernel<<<BH * TT, 64>>>(rph, rpw);
    scores_gemm<<<dim3(8, 96), 256, sizeof(SmemS)>>>();
    pv_gemm<<<dim3(8, 96), 256, sizeof(SmemG)>>>();
    out_gemm<<<dim3(12, 64), 256, sizeof(SmemG)>>>(Wo, bo, out);
}

// round 9
// speedup vs baseline: 2.1190x; 1.6601x over previous
#include <cuda_runtime.h>
#include <math.h>

#define BB 8
#define TT 1024
#define CC 768
#define HH 12
#define DD 64
#define BH (BB*HH)          // 96
#define BT (BB*TT)          // 8192
#define SCALE 0.125f

// ---------------- scratch (device globals; no allocation allowed) ----------------
__device__ float g_xT[CC*BT];                    // x transposed   [c][m]
__device__ float g_cT[CC*BT];                    // ctx transposed [c][m]
__device__ float g_q [BT*CC];                    // q natural (relbias)
__device__ float g_qT[BH*DD*TT];                 // q  [bh][d][q]
__device__ float g_kT[BH*DD*TT];                 // k  [bh][d][key]
__device__ float g_v [BT*CC];                    // v natural (pv B)
__device__ float g_oT[CC*BT];                    // attention out transposed [c][m]
__device__ float g_relh[BH*TT*32];
__device__ float g_relw[BH*TT*32];
__device__ float g_att[(size_t)BH*TT*TT];        // raw biased scores
__device__ float g_m[BH*TT];
__device__ float g_l[BH*TT];

// ---------------- packed fp32x2 + async helpers ----------------------------------
typedef unsigned long long ull;
__device__ __forceinline__ ull bc2(float v) {
    ull r; asm("mov.b64 %0, {%1, %1};" : "=l"(r) : "f"(v)); return r;
}
__device__ __forceinline__ void ffma2(ull& d, ull a, ull b) {
    asm("fma.rn.f32x2 %0, %1, %2, %0;" : "+l"(d) : "l"(a), "l"(b));
}
__device__ __forceinline__ float2 up2(ull v) {
    float2 f; asm("mov.b64 {%0, %1}, %2;" : "=f"(f.x), "=f"(f.y) : "l"(v)); return f;
}
__device__ __forceinline__ unsigned s2u(const void* p) {
    unsigned a;
    asm("{ .reg .u64 t; cvta.to.shared.u64 t, %1; cvt.u32.u64 %0, t; }" : "=r"(a) : "l"(p));
    return a;
}
__device__ __forceinline__ void cpa16(unsigned dst, const float* src) {
    asm volatile("cp.async.cg.shared.global [%0], [%1], 16;" :: "r"(dst), "l"(src) : "memory");
}
#define CP_COMMIT() asm volatile("cp.async.commit_group;" ::: "memory")
#define CP_WAIT0()  asm volatile("cp.async.wait_group 0;" ::: "memory")
#define CP_WAIT1()  asm volatile("cp.async.wait_group 1;" ::: "memory")

#define LDA 132      // floats, [k][m] tile stride (m=128)
#define LDB 68       // floats, [k][n] tile stride (n=64)

struct SmemG { float As[2][32][LDA]; float Bs[2][32][LDB]; };        // 51200 B
struct SmemS {                                                        // 101376 B
    float Qs[64][LDA];
    float Kt[2][64][LDB];
    float rh[128][32];
    float rw[128][32];
};

// one k-step batch: acc[nj][mpair]  (16 FFMA2, 3 LDS.128, 4 MOV)
#define KSTEP(AS, BS, kk)                                              \
    {                                                                  \
        ulonglong2 a01 = *(const ulonglong2*)&(AS)[kk][tm];            \
        ulonglong2 a23 = *(const ulonglong2*)&(AS)[kk][tm + 4];        \
        float4 bv = *(const float4*)&(BS)[kk][tn];                     \
        ull b0 = bc2(bv.x), b1 = bc2(bv.y), b2 = bc2(bv.z), b3 = bc2(bv.w); \
        ffma2(acc[0][0], a01.x, b0); ffma2(acc[0][1], a01.y, b0);      \
        ffma2(acc[0][2], a23.x, b0); ffma2(acc[0][3], a23.y, b0);      \
        ffma2(acc[1][0], a01.x, b1); ffma2(acc[1][1], a01.y, b1);      \
        ffma2(acc[1][2], a23.x, b1); ffma2(acc[1][3], a23.y, b1);      \
        ffma2(acc[2][0], a01.x, b2); ffma2(acc[2][1], a01.y, b2);      \
        ffma2(acc[2][2], a23.x, b2); ffma2(acc[2][3], a23.y, b2);      \
        ffma2(acc[3][0], a01.x, b3); ffma2(acc[3][1], a01.y, b3);      \
        ffma2(acc[3][2], a23.x, b3); ffma2(acc[3][3], a23.y, b3);      \
    }

// =================================================================================
// transpose_in: xT/cT [c][m] from x/ctx [m][c]. grid (256, 24, 2), block (32,8).
// =================================================================================
__global__ void __launch_bounds__(256) transpose_in(const float* __restrict__ x,
                                                    const float* __restrict__ ctx)
{
    __shared__ float t[32][33];
    const float* src = blockIdx.z ? ctx : x;
    float* dst = blockIdx.z ? g_cT : g_xT;
    const int m0 = blockIdx.x * 32, c0 = blockIdx.y * 32;
    const int tx = threadIdx.x, ty = threadIdx.y;
#pragma unroll
    for (int i = 0; i < 4; i++)
        t[ty + 8 * i][tx] = src[(size_t)(m0 + ty + 8 * i) * CC + c0 + tx];
    __syncthreads();
#pragma unroll
    for (int i = 0; i < 4; i++)
        dst[(size_t)(c0 + ty + 8 * i) * BT + m0 + tx] = t[tx][ty + 8 * i];
}

// =================================================================================
// qkv: one projection GEMM per launch (z selects). Tile 128x64, BK=32, cp.async.
// grid (12, 64), 256 thr.
// =================================================================================
__global__ void __launch_bounds__(256, 2) qkv_gemm(int z, const float* __restrict__ W)
{
    extern __shared__ char smraw[];
    SmemG& S = *(SmemG*)smraw;
    const unsigned sb = s2u(smraw);
    const float* AT = (z == 0) ? g_xT : g_cT;

    const int tid = threadIdx.x;
    const int n0 = blockIdx.x * 64, m0 = blockIdx.y * 128;
    const int tm = (tid >> 4) * 8, tn = (tid & 15) * 4;

    ull acc[4][4];
#pragma unroll
    for (int j = 0; j < 4; j++)
#pragma unroll
        for (int p = 0; p < 4; p++) acc[j][p] = 0ull;

    {
#pragma unroll
        for (int i = 0; i < 4; i++) {
            int idx = tid + 256 * i;
            int r = idx >> 5, c = idx & 31;
            cpa16(sb + (unsigned)(r * LDA + c * 4) * 4,
                  AT + (size_t)r * BT + m0 + c * 4);
        }
#pragma unroll
        for (int i = 0; i < 2; i++) {
            int idx = tid + 256 * i;
            int r = idx >> 4, c = idx & 15;
            cpa16(sb + (unsigned)(2 * 32 * LDA * 4) + (unsigned)((0 * 32 + r) * LDB + c * 4) * 4,
                  W + (size_t)r * CC + n0 + c * 4);
        }
        CP_COMMIT();
    }

    for (int kt = 0; kt < 24; kt++) {
        if (kt < 23) {
            const int k0 = (kt + 1) * 32;
            const int buf = (kt + 1) & 1;
#pragma unroll
            for (int i = 0; i < 4; i++) {
                int idx = tid + 256 * i;
                int r = idx >> 5, c = idx & 31;
                cpa16(sb + (unsigned)((buf * 32 + r) * LDA + c * 4) * 4,
                      AT + (size_t)(k0 + r) * BT + m0 + c * 4);
            }
#pragma unroll
            for (int i = 0; i < 2; i++) {
                int idx = tid + 256 * i;
                int r = idx >> 4, c = idx & 15;
                cpa16(sb + (unsigned)(2 * 32 * LDA * 4) + (unsigned)((buf * 32 + r) * LDB + c * 4) * 4,
                      W + (size_t)(k0 + r) * CC + n0 + c * 4);
            }
            CP_COMMIT();
            CP_WAIT1();
        } else {
            CP_WAIT0();
        }
        __syncthreads();
        const int b = kt & 1;
#pragma unroll 16
        for (int kk = 0; kk < 32; kk++) KSTEP(S.As[b], S.Bs[b], kk)
        __syncthreads();
    }

    // ---- epilogue: natural writes (q, v) direct; transposed (q, k) via smem ----
#pragma unroll
    for (int p = 0; p < 4; p++) {
        float2 u[4];
#pragma unroll
        for (int j = 0; j < 4; j++) u[j] = up2(acc[j][p]);
        const int mlo = m0 + tm + 2 * p;
        if (z == 0) {
            *(float4*)&g_q[(size_t)mlo * CC + n0 + tn]       = make_float4(u[0].x, u[1].x, u[2].x, u[3].x);
            *(float4*)&g_q[(size_t)(mlo + 1) * CC + n0 + tn] = make_float4(u[0].y, u[1].y, u[2].y, u[3].y);
        } else if (z == 2) {
            *(float4*)&g_v[(size_t)mlo * CC + n0 + tn]       = make_float4(u[0].x, u[1].x, u[2].x, u[3].x);
            *(float4*)&g_v[(size_t)(mlo + 1) * CC + n0 + tn] = make_float4(u[0].y, u[1].y, u[2].y, u[3].y);
        }
    }
    if (z <= 1) {
        float* T = (float*)smraw;            // 64 x LDA staging (fits in As)
#pragma unroll
        for (int p = 0; p < 4; p++) {
#pragma unroll
            for (int j = 0; j < 4; j++) {
                float2 u = up2(acc[j][p]);
                T[(tn + j) * LDA + tm + 2 * p]     = u.x;
                T[(tn + j) * LDA + tm + 2 * p + 1] = u.y;
            }
        }
        __syncthreads();
        float* Tt = (z == 0) ? g_qT : g_kT;
        const int b2 = m0 >> 10, qb = m0 & 1023;
#pragma unroll
        for (int i = 0; i < 8; i++) {
            int idx = tid + 256 * i;             // 2048 float4
            int r = idx >> 5, c4 = (idx & 31) * 4;
            const int n = n0 + r, h = n >> 6, d = n & 63;
            *(float4*)&Tt[(size_t)((b2 * HH + h) * DD + d) * TT + qb + c4] =
                *(const float4*)&T[r * LDA + c4];
        }
    }
}

// =================================================================================
// relbias v2: coalesced. Each warp reduces over channels (lanes span c via float2),
// one output per shuffle-reduce. Warp 0 -> relh, warp 1 -> relw. grid BH*TT, 64 thr.
// Old version gathered 32 rows at stride 256B per LDG (nL=32 wavefronts) — L1 killer.
// =================================================================================
__global__ void __launch_bounds__(64) relbias_kernel(const float* __restrict__ rph,
                                                     const float* __restrict__ rpw)
{
    const int bq = blockIdx.x;
    const int bh = bq >> 10;
    const int q  = bq & 1023;
    const int b = bh / HH, h = bh % HH;
    const int i = q >> 5, j = q & 31;
    const int t = threadIdx.x;
    const int lane = t & 31, w = t >> 5;

    __shared__ float qs[64];
    qs[t] = g_q[(size_t)(b * TT + q) * CC + h * DD + t];
    __syncthreads();

    const float2 qv = *(const float2*)&qs[2 * lane];
    const float* tab0 = w ? (rpw + (size_t)(j + 31) * DD)
                          : (rph + (size_t)(i + 31) * DD);
    float* outp = (w ? g_relw : g_relh) + (size_t)bq * 32;

#pragma unroll 8
    for (int k = 0; k < 32; k++) {
        float2 tv = *(const float2*)(tab0 - (size_t)k * DD + 2 * lane);
        float p = fmaf(qv.x, tv.x, qv.y * tv.y);
#pragma unroll
        for (int off = 16; off; off >>= 1)
            p += __shfl_xor_sync(0xffffffffu, p, off);
        if (lane == 0) outp[k] = p;
    }
}

// =================================================================================
// scores: S = Q K^T * SCALE + bias -> g_att; per-thread local online (m,l),
// merged across lanes once at the end. grid (8, 96), 256 thr.
// =================================================================================
__global__ void __launch_bounds__(256, 2) scores_gemm()
{
    extern __shared__ char smraw[];
    SmemS& S = *(SmemS*)smraw;
    const unsigned sb = s2u(smraw);
    const int z = blockIdx.y;
    const int m0 = blockIdx.x * 128;
    const int tid = threadIdx.x;
    const int tm = (tid >> 4) * 8, tn = (tid & 15) * 4;

    const unsigned off_K  = (unsigned)(64 * LDA * 4);
    const unsigned off_rh = off_K + (unsigned)(2 * 64 * LDB * 4);
    const unsigned off_rw = off_rh + 128 * 32 * 4;

#pragma unroll
    for (int i = 0; i < 8; i++) {
        int idx = tid + 256 * i;
        int r = idx >> 5, c = idx & 31;
        cpa16(sb + (unsigned)(r * LDA + c * 4) * 4,
              g_qT + (size_t)(z * DD + r) * TT + m0 + c * 4);
    }
#pragma unroll
    for (int i = 0; i < 4; i++) {
        int idx = tid + 256 * i;
        int r = idx >> 3, c = idx & 7;
        cpa16(sb + off_rh + (unsigned)(r * 32 + c * 4) * 4,
              g_relh + (size_t)(z * TT + m0 + r) * 32 + c * 4);
        cpa16(sb + off_rw + (unsigned)(r * 32 + c * 4) * 4,
              g_relw + (size_t)(z * TT + m0 + r) * 32 + c * 4);
    }
#pragma unroll
    for (int i = 0; i < 4; i++) {
        int idx = tid + 256 * i;
        int r = idx >> 4, c = idx & 15;
        cpa16(sb + off_K + (unsigned)(r * LDB + c * 4) * 4,
              g_kT + (size_t)(z * DD + r) * TT + c * 4);
    }
    CP_COMMIT();

    float mloc[8], lloc[8];
#pragma unroll
    for (int r = 0; r < 8; r++) { mloc[r] = -INFINITY; lloc[r] = 0.0f; }

    const int khi_base = tn >> 5;
    const int tnm = tn & 31;

    for (int nt = 0; nt < 16; nt++) {
        if (nt < 15) {
            const int buf = (nt + 1) & 1;
#pragma unroll
            for (int i = 0; i < 4; i++) {
                int idx = tid + 256 * i;
                int r = idx >> 4, c = idx & 15;
                cpa16(sb + off_K + (unsigned)((buf * 64 + r) * LDB + c * 4) * 4,
                      g_kT + (size_t)(z * DD + r) * TT + (nt + 1) * 64 + c * 4);
            }
            CP_COMMIT();
            CP_WAIT1();
        } else {
            CP_WAIT0();
        }
        __syncthreads();

        ull acc[4][4];
#pragma unroll
        for (int j = 0; j < 4; j++)
#pragma unroll
            for (int p = 0; p < 4; p++) acc[j][p] = 0ull;

        const float (*Kc)[LDB] = S.Kt[nt & 1];
#pragma unroll 16
        for (int kk = 0; kk < 64; kk++) KSTEP(S.Qs, Kc, kk)

        const int khi = nt * 2 + khi_base;
#pragma unroll
        for (int p = 0; p < 4; p++) {
            float2 u[4];
#pragma unroll
            for (int j = 0; j < 4; j++) u[j] = up2(acc[j][p]);
#pragma unroll
            for (int half = 0; half < 2; half++) {
                const int r = 2 * p + half;
                const int rl = tm + r;
                const float bh = S.rh[rl][khi];
                float s0 = fmaf(half ? u[0].y : u[0].x, SCALE, bh + S.rw[rl][tnm]);
                float s1 = fmaf(half ? u[1].y : u[1].x, SCALE, bh + S.rw[rl][tnm + 1]);
                float s2 = fmaf(half ? u[2].y : u[2].x, SCALE, bh + S.rw[rl][tnm + 2]);
                float s3 = fmaf(half ? u[3].y : u[3].x, SCALE, bh + S.rw[rl][tnm + 3]);
                float tmax = fmaxf(fmaxf(s0, s1), fmaxf(s2, s3));
                const float mn = fmaxf(mloc[r], tmax);
                lloc[r] = lloc[r] * __expf(mloc[r] - mn)
                        + __expf(s0 - mn) + __expf(s1 - mn)
                        + __expf(s2 - mn) + __expf(s3 - mn);
                mloc[r] = mn;
                *(float4*)&g_att[((size_t)z * TT + m0 + rl) * TT + nt * 64 + tn] =
                    make_float4(s0, s1, s2, s3);
            }
        }
        __syncthreads();
    }

#pragma unroll
    for (int r = 0; r < 8; r++) {
        float mm = mloc[r], ll = lloc[r];
#pragma unroll
        for (int off = 1; off < 16; off <<= 1) {
            float mo  = __shfl_xor_sync(0xffffffffu, mm, off);
            float lo_ = __shfl_xor_sync(0xffffffffu, ll, off);
            float mn = fmaxf(mm, mo);
            ll = ll * __expf(mm - mn) + lo_ * __expf(mo - mn);
            mm = mn;
        }
        if ((tid & 15) == 0) {
            g_m[z * TT + m0 + tm + r] = mm;
            g_l[z * TT + m0 + tm + r] = ll;
        }
    }
}

// =================================================================================
// pv: oT = (softmax(S) @ V)^T. A staged w/ expf; B via cp.async. grid (8, 96).
// =================================================================================
__global__ void __launch_bounds__(256, 2) pv_gemm()
{
    extern __shared__ char smraw[];
    SmemG& S = *(SmemG*)smraw;
    const unsigned sb = s2u(smraw);
    const int z = blockIdx.y, b = z / HH, h = z % HH;
    const int m0 = blockIdx.x * 128;
    const int tid = threadIdx.x;
    const int tm = (tid >> 4) * 8, tn = (tid & 15) * 4;
    const int ar = tid >> 3, akq = (tid & 7) * 4;
    const unsigned off_B = (unsigned)(2 * 32 * LDA * 4);

    const float* att = g_att + ((size_t)z * TT + m0) * TT;
    const float* vb  = g_v + (size_t)(b * TT) * CC + h * DD;

    float mrow[4];
#pragma unroll
    for (int i = 0; i < 4; i++) mrow[i] = g_m[z * TT + m0 + ar + 32 * i];

    ull acc[4][4];
#pragma unroll
    for (int j = 0; j < 4; j++)
#pragma unroll
        for (int p = 0; p < 4; p++) acc[j][p] = 0ull;

    {
#pragma unroll
        for (int i = 0; i < 2; i++) {
            int idx = tid + 256 * i;
            int r = idx >> 4, c = idx & 15;
            cpa16(sb + off_B + (unsigned)(r * LDB + c * 4) * 4,
                  vb + (size_t)r * CC + c * 4);
        }
        CP_COMMIT();
#pragma unroll
        for (int i = 0; i < 4; i++) {
            float4 v = *(const float4*)&att[(size_t)(ar + 32 * i) * TT + akq];
            S.As[0][akq + 0][ar + 32 * i] = __expf(v.x - mrow[i]);
            S.As[0][akq + 1][ar + 32 * i] = __expf(v.y - mrow[i]);
            S.As[0][akq + 2][ar + 32 * i] = __expf(v.z - mrow[i]);
            S.As[0][akq + 3][ar + 32 * i] = __expf(v.w - mrow[i]);
        }
    }

    float4 fa[4];
    for (int kt = 0; kt < 32; kt++) {
        if (kt < 31) {
            const int k0 = (kt + 1) * 32;
            const int buf = (kt + 1) & 1;
#pragma unroll
            for (int i = 0; i < 2; i++) {
                int idx = tid + 256 * i;
                int r = idx >> 4, c = idx & 15;
                cpa16(sb + off_B + (unsigned)((buf * 32 + r) * LDB + c * 4) * 4,
                      vb + (size_t)(k0 + r) * CC + c * 4);
            }
            CP_COMMIT();
#pragma unroll
            for (int i = 0; i < 4; i++)
                fa[i] = *(const float4*)&att[(size_t)(ar + 32 * i) * TT + k0 + akq];
            CP_WAIT1();
        } else {
            CP_WAIT0();
        }
        __syncthreads();
        const int bf = kt & 1;
#pragma unroll 16
        for (int kk = 0; kk < 32; kk++) KSTEP(S.As[bf], S.Bs[bf], kk)
        __syncthreads();
        if (kt < 31) {
            const int nb = (kt + 1) & 1;
#pragma unroll
            for (int i = 0; i < 4; i++) {
                S.As[nb][akq + 0][ar + 32 * i] = __expf(fa[i].x - mrow[i]);
                S.As[nb][akq + 1][ar + 32 * i] = __expf(fa[i].y - mrow[i]);
                S.As[nb][akq + 2][ar + 32 * i] = __expf(fa[i].z - mrow[i]);
                S.As[nb][akq + 3][ar + 32 * i] = __expf(fa[i].w - mrow[i]);
            }
        }
    }

    // ---- epilogue: stage through smem, write g_oT coalesced ----
    __syncthreads();
    float* T = (float*)smraw;                // 64 x LDA staging
#pragma unroll
    for (int p = 0; p < 4; p++) {
        const int mlo = m0 + tm + 2 * p;
        const float i0 = 1.0f / g_l[z * TT + mlo];
        const float i1 = 1.0f / g_l[z * TT + mlo + 1];
#pragma unroll
        for (int j = 0; j < 4; j++) {
            float2 u = up2(acc[j][p]);
            T[(tn + j) * LDA + tm + 2 * p]     = u.x * i0;
            T[(tn + j) * LDA + tm + 2 * p + 1] = u.y * i1;
        }
    }
    __syncthreads();
#pragma unroll
    for (int i = 0; i < 8; i++) {
        int idx = tid + 256 * i;                 // 2048 float4
        int r = idx >> 5, c4 = (idx & 31) * 4;
        *(float4*)&g_oT[(size_t)(h * DD + r) * BT + b * TT + m0 + c4] =
            *(const float4*)&T[r * LDA + c4];
    }
}

// =================================================================================
// out: out = oT^T @ Wo + bo. grid (12, 64).
// =================================================================================
__global__ void __launch_bounds__(256, 2) out_gemm(const float* __restrict__ Wo,
                                                   const float* __restrict__ bo,
                                                   float* __restrict__ Out)
{
    extern __shared__ char smraw[];
    SmemG& S = *(SmemG*)smraw;
    const unsigned sb = s2u(smraw);
    const int tid = threadIdx.x;
    const int n0 = blockIdx.x * 64, m0 = blockIdx.y * 128;
    const int tm = (tid >> 4) * 8, tn = (tid & 15) * 4;
    const unsigned off_B = (unsigned)(2 * 32 * LDA * 4);

    ull acc[4][4];
#pragma unroll
    for (int j = 0; j < 4; j++)
#pragma unroll
        for (int p = 0; p < 4; p++) acc[j][p] = 0ull;

    {
#pragma unroll
        for (int i = 0; i < 4; i++) {
            int idx = tid + 256 * i;
            int r = idx >> 5, c = idx & 31;
            cpa16(sb + (unsigned)(r * LDA + c * 4) * 4,
                  g_oT + (size_t)r * BT + m0 + c * 4);
        }
#pragma unroll
        for (int i = 0; i < 2; i++) {
            int idx = tid + 256 * i;
            int r = idx >> 4, c = idx & 15;
            cpa16(sb + off_B + (unsigned)(r * LDB + c * 4) * 4,
                  Wo + (size_t)r * CC + n0 + c * 4);
        }
        CP_COMMIT();
    }

    for (int kt = 0; kt < 24; kt++) {
        if (kt < 23) {
            const int k0 = (kt + 1) * 32;
            const int buf = (kt + 1) & 1;
#pragma unroll
            for (int i = 0; i < 4; i++) {
                int idx = tid + 256 * i;
                int r = idx >> 5, c = idx & 31;
                cpa16(sb + (unsigned)((buf * 32 + r) * LDA + c * 4) * 4,
                      g_oT + (size_t)(k0 + r) * BT + m0 + c * 4);
            }
#pragma unroll
            for (int i = 0; i < 2; i++) {
                int idx = tid + 256 * i;
                int r = idx >> 4, c = idx & 15;
                cpa16(sb + off_B + (unsigned)((buf * 32 + r) * LDB + c * 4) * 4,
                      Wo + (size_t)(k0 + r) * CC + n0 + c * 4);
            }
            CP_COMMIT();
            CP_WAIT1();
        } else {
            CP_WAIT0();
        }
        __syncthreads();
        const int b = kt & 1;
#pragma unroll 16
        for (int kk = 0; kk < 32; kk++) KSTEP(S.As[b], S.Bs[b], kk)
        __syncthreads();
    }

    const float4 bv = *(const float4*)&bo[n0 + tn];
#pragma unroll
    for (int p = 0; p < 4; p++) {
        float2 u[4];
#pragma unroll
        for (int j = 0; j < 4; j++) u[j] = up2(acc[j][p]);
        const int mlo = m0 + tm + 2 * p;
        *(float4*)&Out[(size_t)mlo * CC + n0 + tn] =
            make_float4(u[0].x + bv.x, u[1].x + bv.y, u[2].x + bv.z, u[3].x + bv.w);
        *(float4*)&Out[(size_t)(mlo + 1) * CC + n0 + tn] =
            make_float4(u[0].y + bv.x, u[1].y + bv.y, u[2].y + bv.z, u[3].y + bv.w);
    }
}

// =================================================================================
extern "C" void kernel_launch(void* const* d_in, const int* in_sizes, int n_in,
                              void* d_out, int out_size)
{
    const float* x   = (const float*)d_in[0];
    const float* ctx = (const float*)d_in[1];
    const float* Wq  = (const float*)d_in[2];
    const float* Wk  = (const float*)d_in[3];
    const float* Wv  = (const float*)d_in[4];
    const float* Wo  = (const float*)d_in[5];
    const float* bo  = (const float*)d_in[6];
    const float* rph = (const float*)d_in[7];
    const float* rpw = (const float*)d_in[8];
    float* out = (float*)d_out;

    cudaFuncSetAttribute(qkv_gemm,    cudaFuncAttributeMaxDynamicSharedMemorySize, (int)sizeof(SmemG));
    cudaFuncSetAttribute(out_gemm,    cudaFuncAttributeMaxDynamicSharedMemorySize, (int)sizeof(SmemG));
    cudaFuncSetAttribute(pv_gemm,     cudaFuncAttributeMaxDynamicSharedMemorySize, (int)sizeof(SmemG));
    cudaFuncSetAttribute(scores_gemm, cudaFuncAttributeMaxDynamicSharedMemorySize, (int)sizeof(SmemS));

    // launch order chosen so ncu's fixed sample lands on qkv z=0 (launch #4)
    transpose_in<<<dim3(256, 24, 2), dim3(32, 8)>>>(x, ctx);
    qkv_gemm<<<dim3(12, 64), 256, sizeof(SmemG)>>>(1, Wk);
    qkv_gemm<<<dim3(12, 64), 256, sizeof(SmemG)>>>(2, Wv);
    qkv_gemm<<<dim3(12, 64), 256, sizeof(SmemG)>>>(0, Wq);   // <- profiled
    relbias_kernel<<<BH * TT, 64>>>(rph, rpw);
    scores_gemm<<<dim3(8, 96), 256, sizeof(SmemS)>>>();
    pv_gemm<<<dim3(8, 96), 256, sizeof(SmemG)>>>();
    out_gemm<<<dim3(12, 64), 256, sizeof(SmemG)>>>(Wo, bo, out);
}

// round 10
// speedup vs baseline: 2.1352x; 1.0076x over previous
#include <cuda_runtime.h>
#include <math.h>

#define BB 8
#define TT 1024
#define CC 768
#define HH 12
#define DD 64
#define BH (BB*HH)          // 96
#define BT (BB*TT)          // 8192
#define SCALE 0.125f

// ---------------- scratch (device globals; no allocation allowed) ----------------
__device__ float g_xT[CC*BT];                    // x transposed   [c][m]
__device__ float g_cT[CC*BT];                    // ctx transposed [c][m]
__device__ float g_q [BT*CC];                    // q natural (relbias)
__device__ float g_qT[BH*DD*TT];                 // q  [bh][d][q]
__device__ float g_kT[BH*DD*TT];                 // k  [bh][d][key]
__device__ float g_v [BT*CC];                    // v natural (pv B)
__device__ float g_oT[CC*BT];                    // attention out transposed [c][m]
__device__ float g_relh[BH*TT*32];
__device__ float g_relw[BH*TT*32];
__device__ float g_att[(size_t)BH*TT*TT];        // raw biased scores
__device__ float g_m[BH*TT];
__device__ float g_l[BH*TT];

// ---------------- packed fp32x2 + async helpers ----------------------------------
typedef unsigned long long ull;
__device__ __forceinline__ ull bc2(float v) {
    ull r; asm("mov.b64 %0, {%1, %1};" : "=l"(r) : "f"(v)); return r;
}
__device__ __forceinline__ void ffma2(ull& d, ull a, ull b) {
    asm("fma.rn.f32x2 %0, %1, %2, %0;" : "+l"(d) : "l"(a), "l"(b));
}
__device__ __forceinline__ float2 up2(ull v) {
    float2 f; asm("mov.b64 {%0, %1}, %2;" : "=f"(f.x), "=f"(f.y) : "l"(v)); return f;
}
__device__ __forceinline__ unsigned s2u(const void* p) {
    unsigned a;
    asm("{ .reg .u64 t; cvta.to.shared.u64 t, %1; cvt.u32.u64 %0, t; }" : "=r"(a) : "l"(p));
    return a;
}
__device__ __forceinline__ void cpa16(unsigned dst, const float* src) {
    asm volatile("cp.async.cg.shared.global [%0], [%1], 16;" :: "r"(dst), "l"(src) : "memory");
}
#define CP_COMMIT() asm volatile("cp.async.commit_group;" ::: "memory")
#define CP_WAIT0()  asm volatile("cp.async.wait_group 0;" ::: "memory")
#define CP_WAIT1()  asm volatile("cp.async.wait_group 1;" ::: "memory")

#define LDA 132      // floats, [k][m] tile stride (m=128)
#define LDB 68       // floats, [k][n] tile stride (n=64)

// 3-stage ring for qkv/out; A-double + B-triple for pv; scores keeps 2-buf K.
struct SmemG3 { float As[3][32][LDA]; float Bs[3][32][LDB]; };       // 76800 B
struct SmemPV { float As[2][32][LDA]; float Bs[3][32][LDB]; };       // 59904 B
struct SmemS {                                                        // 101376 B
    float Qs[64][LDA];
    float Kt[2][64][LDB];
    float rh[128][32];
    float rw[128][32];
};

// one k-step batch: acc[nj][mpair]  (16 FFMA2, 3 LDS.128, 4 MOV)
#define KSTEP(AS, BS, kk)                                              \
    {                                                                  \
        ulonglong2 a01 = *(const ulonglong2*)&(AS)[kk][tm];            \
        ulonglong2 a23 = *(const ulonglong2*)&(AS)[kk][tm + 4];        \
        float4 bv = *(const float4*)&(BS)[kk][tn];                     \
        ull b0 = bc2(bv.x), b1 = bc2(bv.y), b2 = bc2(bv.z), b3 = bc2(bv.w); \
        ffma2(acc[0][0], a01.x, b0); ffma2(acc[0][1], a01.y, b0);      \
        ffma2(acc[0][2], a23.x, b0); ffma2(acc[0][3], a23.y, b0);      \
        ffma2(acc[1][0], a01.x, b1); ffma2(acc[1][1], a01.y, b1);      \
        ffma2(acc[1][2], a23.x, b1); ffma2(acc[1][3], a23.y, b1);      \
        ffma2(acc[2][0], a01.x, b2); ffma2(acc[2][1], a01.y, b2);      \
        ffma2(acc[2][2], a23.x, b2); ffma2(acc[2][3], a23.y, b2);      \
        ffma2(acc[3][0], a01.x, b3); ffma2(acc[3][1], a01.y, b3);      \
        ffma2(acc[3][2], a23.x, b3); ffma2(acc[3][3], a23.y, b3);      \
    }

#define WRAP3(s) ((s) == 2 ? 0 : (s) + 1)

// =================================================================================
// transpose_in: xT/cT [c][m] from x/ctx [m][c]. grid (256, 24, 2), block (32,8).
// =================================================================================
__global__ void __launch_bounds__(256) transpose_in(const float* __restrict__ x,
                                                    const float* __restrict__ ctx)
{
    __shared__ float t[32][33];
    const float* src = blockIdx.z ? ctx : x;
    float* dst = blockIdx.z ? g_cT : g_xT;
    const int m0 = blockIdx.x * 32, c0 = blockIdx.y * 32;
    const int tx = threadIdx.x, ty = threadIdx.y;
#pragma unroll
    for (int i = 0; i < 4; i++)
        t[ty + 8 * i][tx] = src[(size_t)(m0 + ty + 8 * i) * CC + c0 + tx];
    __syncthreads();
#pragma unroll
    for (int i = 0; i < 4; i++)
        dst[(size_t)(c0 + ty + 8 * i) * BT + m0 + tx] = t[tx][ty + 8 * i];
}

// =================================================================================
// qkv: one projection GEMM per launch. Tile 128x64, BK=32.
// 3-stage cp.async ring, ONE barrier per k-iter. grid (12, 64), 256 thr.
// =================================================================================
__global__ void __launch_bounds__(256, 2) qkv_gemm(int z, const float* __restrict__ W)
{
    extern __shared__ char smraw[];
    SmemG3& S = *(SmemG3*)smraw;
    const unsigned sb = s2u(smraw);
    const unsigned OFFB = (unsigned)(3 * 32 * LDA * 4);
    const float* AT = (z == 0) ? g_xT : g_cT;

    const int tid = threadIdx.x;
    const int n0 = blockIdx.x * 64, m0 = blockIdx.y * 128;
    const int tm = (tid >> 4) * 8, tn = (tid & 15) * 4;

    ull acc[4][4];
#pragma unroll
    for (int j = 0; j < 4; j++)
#pragma unroll
        for (int p = 0; p < 4; p++) acc[j][p] = 0ull;

    auto issue = [&](int st, int kb) {
        const float* Ab = AT + (size_t)kb * 32 * BT + m0;
        const float* Bb = W  + (size_t)kb * 32 * CC + n0;
#pragma unroll
        for (int i = 0; i < 4; i++) {
            int idx = tid + 256 * i;
            int r = idx >> 5, c = idx & 31;
            cpa16(sb + (unsigned)((st * 32 + r) * LDA + c * 4) * 4,
                  Ab + (size_t)r * BT + c * 4);
        }
#pragma unroll
        for (int i = 0; i < 2; i++) {
            int idx = tid + 256 * i;
            int r = idx >> 4, c = idx & 15;
            cpa16(sb + OFFB + (unsigned)((st * 32 + r) * LDB + c * 4) * 4,
                  Bb + (size_t)r * CC + c * 4);
        }
        CP_COMMIT();
    };

    issue(0, 0);
    issue(1, 1);

    int stC = 0, stI = 2;
    for (int kt = 0; kt < 24; kt++) {
        if (kt < 23) CP_WAIT1(); else CP_WAIT0();
        __syncthreads();
        if (kt < 22) { issue(stI, kt + 2); stI = WRAP3(stI); }
        const float (*Asb)[LDA] = S.As[stC];
        const float (*Bsb)[LDB] = S.Bs[stC];
#pragma unroll 16
        for (int kk = 0; kk < 32; kk++) KSTEP(Asb, Bsb, kk)
        stC = WRAP3(stC);
    }

    // ---- epilogue: natural writes (q, v) direct; transposed (q, k) via smem ----
#pragma unroll
    for (int p = 0; p < 4; p++) {
        float2 u[4];
#pragma unroll
        for (int j = 0; j < 4; j++) u[j] = up2(acc[j][p]);
        const int mlo = m0 + tm + 2 * p;
        if (z == 0) {
            *(float4*)&g_q[(size_t)mlo * CC + n0 + tn]       = make_float4(u[0].x, u[1].x, u[2].x, u[3].x);
            *(float4*)&g_q[(size_t)(mlo + 1) * CC + n0 + tn] = make_float4(u[0].y, u[1].y, u[2].y, u[3].y);
        } else if (z == 2) {
            *(float4*)&g_v[(size_t)mlo * CC + n0 + tn]       = make_float4(u[0].x, u[1].x, u[2].x, u[3].x);
            *(float4*)&g_v[(size_t)(mlo + 1) * CC + n0 + tn] = make_float4(u[0].y, u[1].y, u[2].y, u[3].y);
        }
    }
    if (z <= 1) {
        __syncthreads();                        // retire last tile reads before reuse
        float* T = (float*)smraw;               // 64 x LDA staging
#pragma unroll
        for (int p = 0; p < 4; p++) {
#pragma unroll
            for (int j = 0; j < 4; j++) {
                float2 u = up2(acc[j][p]);
                T[(tn + j) * LDA + tm + 2 * p]     = u.x;
                T[(tn + j) * LDA + tm + 2 * p + 1] = u.y;
            }
        }
        __syncthreads();
        float* Tt = (z == 0) ? g_qT : g_kT;
        const int b2 = m0 >> 10, qb = m0 & 1023;
#pragma unroll
        for (int i = 0; i < 8; i++) {
            int idx = tid + 256 * i;             // 2048 float4
            int r = idx >> 5, c4 = (idx & 31) * 4;
            const int n = n0 + r, h = n >> 6, d = n & 63;
            *(float4*)&Tt[(size_t)((b2 * HH + h) * DD + d) * TT + qb + c4] =
                *(const float4*)&T[r * LDA + c4];
        }
    }
}

// =================================================================================
// relbias v2 (coalesced; validated round 9: saved ~1 ms vs strided gather)
// =================================================================================
__global__ void __launch_bounds__(64) relbias_kernel(const float* __restrict__ rph,
                                                     const float* __restrict__ rpw)
{
    const int bq = blockIdx.x;
    const int bh = bq >> 10;
    const int q  = bq & 1023;
    const int b = bh / HH, h = bh % HH;
    const int i = q >> 5, j = q & 31;
    const int t = threadIdx.x;
    const int lane = t & 31, w = t >> 5;

    __shared__ float qs[64];
    qs[t] = g_q[(size_t)(b * TT + q) * CC + h * DD + t];
    __syncthreads();

    const float2 qv = *(const float2*)&qs[2 * lane];
    const float* tab0 = w ? (rpw + (size_t)(j + 31) * DD)
                          : (rph + (size_t)(i + 31) * DD);
    float* outp = (w ? g_relw : g_relh) + (size_t)bq * 32;

#pragma unroll 8
    for (int k = 0; k < 32; k++) {
        float2 tv = *(const float2*)(tab0 - (size_t)k * DD + 2 * lane);
        float p = fmaf(qv.x, tv.x, qv.y * tv.y);
#pragma unroll
        for (int off = 16; off; off >>= 1)
            p += __shfl_xor_sync(0xffffffffu, p, off);
        if (lane == 0) outp[k] = p;
    }
}

// =================================================================================
// scores: S = Q K^T * SCALE + bias -> g_att; per-thread local online (m,l).
// 2-buf K ring, ONE barrier per n-tile. grid (8, 96), 256 thr.
// =================================================================================
__global__ void __launch_bounds__(256, 2) scores_gemm()
{
    extern __shared__ char smraw[];
    SmemS& S = *(SmemS*)smraw;
    const unsigned sb = s2u(smraw);
    const int z = blockIdx.y;
    const int m0 = blockIdx.x * 128;
    const int tid = threadIdx.x;
    const int tm = (tid >> 4) * 8, tn = (tid & 15) * 4;

    const unsigned off_K  = (unsigned)(64 * LDA * 4);
    const unsigned off_rh = off_K + (unsigned)(2 * 64 * LDB * 4);
    const unsigned off_rw = off_rh + 128 * 32 * 4;

    auto issueK = [&](int buf, int nt) {
#pragma unroll
        for (int i = 0; i < 4; i++) {
            int idx = tid + 256 * i;
            int r = idx >> 4, c = idx & 15;
            cpa16(sb + off_K + (unsigned)((buf * 64 + r) * LDB + c * 4) * 4,
                  g_kT + (size_t)(z * DD + r) * TT + nt * 64 + c * 4);
        }
        CP_COMMIT();
    };

    // group 0: Q tile, rh, rw, K tile 0
#pragma unroll
    for (int i = 0; i < 8; i++) {
        int idx = tid + 256 * i;
        int r = idx >> 5, c = idx & 31;
        cpa16(sb + (unsigned)(r * LDA + c * 4) * 4,
              g_qT + (size_t)(z * DD + r) * TT + m0 + c * 4);
    }
#pragma unroll
    for (int i = 0; i < 4; i++) {
        int idx = tid + 256 * i;
        int r = idx >> 3, c = idx & 7;
        cpa16(sb + off_rh + (unsigned)(r * 32 + c * 4) * 4,
              g_relh + (size_t)(z * TT + m0 + r) * 32 + c * 4);
        cpa16(sb + off_rw + (unsigned)(r * 32 + c * 4) * 4,
              g_relw + (size_t)(z * TT + m0 + r) * 32 + c * 4);
    }
#pragma unroll
    for (int i = 0; i < 4; i++) {
        int idx = tid + 256 * i;
        int r = idx >> 4, c = idx & 15;
        cpa16(sb + off_K + (unsigned)(r * LDB + c * 4) * 4,
              g_kT + (size_t)(z * DD + r) * TT + c * 4);
    }
    CP_COMMIT();

    float mloc[8], lloc[8];
#pragma unroll
    for (int r = 0; r < 8; r++) { mloc[r] = -INFINITY; lloc[r] = 0.0f; }

    const int khi_base = tn >> 5;
    const int tnm = tn & 31;

    for (int nt = 0; nt < 16; nt++) {
        CP_WAIT0();
        __syncthreads();
        if (nt < 15) issueK((nt + 1) & 1, nt + 1);

        ull acc[4][4];
#pragma unroll
        for (int j = 0; j < 4; j++)
#pragma unroll
            for (int p = 0; p < 4; p++) acc[j][p] = 0ull;

        const float (*Kc)[LDB] = S.Kt[nt & 1];
#pragma unroll 16
        for (int kk = 0; kk < 64; kk++) KSTEP(S.Qs, Kc, kk)

        const int khi = nt * 2 + khi_base;
#pragma unroll
        for (int p = 0; p < 4; p++) {
            float2 u[4];
#pragma unroll
            for (int j = 0; j < 4; j++) u[j] = up2(acc[j][p]);
#pragma unroll
            for (int half = 0; half < 2; half++) {
                const int r = 2 * p + half;
                const int rl = tm + r;
                const float bh = S.rh[rl][khi];
                float s0 = fmaf(half ? u[0].y : u[0].x, SCALE, bh + S.rw[rl][tnm]);
                float s1 = fmaf(half ? u[1].y : u[1].x, SCALE, bh + S.rw[rl][tnm + 1]);
                float s2 = fmaf(half ? u[2].y : u[2].x, SCALE, bh + S.rw[rl][tnm + 2]);
                float s3 = fmaf(half ? u[3].y : u[3].x, SCALE, bh + S.rw[rl][tnm + 3]);
                float tmax = fmaxf(fmaxf(s0, s1), fmaxf(s2, s3));
                const float mn = fmaxf(mloc[r], tmax);
                lloc[r] = lloc[r] * __expf(mloc[r] - mn)
                        + __expf(s0 - mn) + __expf(s1 - mn)
                        + __expf(s2 - mn) + __expf(s3 - mn);
                mloc[r] = mn;
                *(float4*)&g_att[((size_t)z * TT + m0 + rl) * TT + nt * 64 + tn] =
                    make_float4(s0, s1, s2, s3);
            }
        }
    }

#pragma unroll
    for (int r = 0; r < 8; r++) {
        float mm = mloc[r], ll = lloc[r];
#pragma unroll
        for (int off = 1; off < 16; off <<= 1) {
            float mo  = __shfl_xor_sync(0xffffffffu, mm, off);
            float lo_ = __shfl_xor_sync(0xffffffffu, ll, off);
            float mn = fmaxf(mm, mo);
            ll = ll * __expf(mm - mn) + lo_ * __expf(mo - mn);
            mm = mn;
        }
        if ((tid & 15) == 0) {
            g_m[z * TT + m0 + tm + r] = mm;
            g_l[z * TT + m0 + tm + r] = ll;
        }
    }
}

// =================================================================================
// pv: oT = (softmax(S) @ V)^T. A double-buffer via LDG+expf+STS (distance 2),
// B 3-stage cp.async ring. ONE barrier per k-iter. grid (8, 96), 256 thr.
// =================================================================================
__global__ void __launch_bounds__(256, 2) pv_gemm()
{
    extern __shared__ char smraw[];
    SmemPV& S = *(SmemPV*)smraw;
    const unsigned sb = s2u(smraw);
    const unsigned OFFB = (unsigned)(2 * 32 * LDA * 4);
    const int z = blockIdx.y, b = z / HH, h = z % HH;
    const int m0 = blockIdx.x * 128;
    const int tid = threadIdx.x;
    const int tm = (tid >> 4) * 8, tn = (tid & 15) * 4;
    const int ar = tid >> 3, akq = (tid & 7) * 4;

    const float* att = g_att + ((size_t)z * TT + m0) * TT;
    const float* vb  = g_v + (size_t)(b * TT) * CC + h * DD;

    float mrow[4];
#pragma unroll
    for (int i = 0; i < 4; i++) mrow[i] = g_m[z * TT + m0 + ar + 32 * i];

    ull acc[4][4];
#pragma unroll
    for (int j = 0; j < 4; j++)
#pragma unroll
        for (int p = 0; p < 4; p++) acc[j][p] = 0ull;

    auto issueB = [&](int st, int kb) {
        const float* Bb = vb + (size_t)kb * 32 * CC;
#pragma unroll
        for (int i = 0; i < 2; i++) {
            int idx = tid + 256 * i;
            int r = idx >> 4, c = idx & 15;
            cpa16(sb + OFFB + (unsigned)((st * 32 + r) * LDB + c * 4) * 4,
                  Bb + (size_t)r * CC + c * 4);
        }
        CP_COMMIT();
    };

    issueB(0, 0);
    issueB(1, 1);

    // A(0) direct into As[0]; prefetch A(1) into fa
    float4 fa[4];
    {
#pragma unroll
        for (int i = 0; i < 4; i++) {
            float4 v = *(const float4*)&att[(size_t)(ar + 32 * i) * TT + akq];
            S.As[0][akq + 0][ar + 32 * i] = __expf(v.x - mrow[i]);
            S.As[0][akq + 1][ar + 32 * i] = __expf(v.y - mrow[i]);
            S.As[0][akq + 2][ar + 32 * i] = __expf(v.z - mrow[i]);
            S.As[0][akq + 3][ar + 32 * i] = __expf(v.w - mrow[i]);
        }
#pragma unroll
        for (int i = 0; i < 4; i++)
            fa[i] = *(const float4*)&att[(size_t)(ar + 32 * i) * TT + 32 + akq];
    }

    int stC = 0, stI = 2;
    for (int kt = 0; kt < 32; kt++) {
        if (kt < 31) CP_WAIT1(); else CP_WAIT0();
        __syncthreads();
        if (kt < 30) { issueB(stI, kt + 2); stI = WRAP3(stI); }
        if (kt < 31) {
            const int nb = (kt + 1) & 1;
#pragma unroll
            for (int i = 0; i < 4; i++) {
                S.As[nb][akq + 0][ar + 32 * i] = __expf(fa[i].x - mrow[i]);
                S.As[nb][akq + 1][ar + 32 * i] = __expf(fa[i].y - mrow[i]);
                S.As[nb][akq + 2][ar + 32 * i] = __expf(fa[i].z - mrow[i]);
                S.As[nb][akq + 3][ar + 32 * i] = __expf(fa[i].w - mrow[i]);
            }
            if (kt < 30) {
                const int k0 = (kt + 2) * 32;
#pragma unroll
                for (int i = 0; i < 4; i++)
                    fa[i] = *(const float4*)&att[(size_t)(ar + 32 * i) * TT + k0 + akq];
            }
        }
        const float (*Asb)[LDA] = S.As[kt & 1];
        const float (*Bsb)[LDB] = S.Bs[stC];
#pragma unroll 16
        for (int kk = 0; kk < 32; kk++) KSTEP(Asb, Bsb, kk)
        stC = WRAP3(stC);
    }

    // ---- epilogue: stage through smem, write g_oT coalesced ----
    __syncthreads();
    float* T = (float*)smraw;                // 64 x LDA staging
#pragma unroll
    for (int p = 0; p < 4; p++) {
        const int mlo = m0 + tm + 2 * p;
        const float i0 = 1.0f / g_l[z * TT + mlo];
        const float i1 = 1.0f / g_l[z * TT + mlo + 1];
#pragma unroll
        for (int j = 0; j < 4; j++) {
            float2 u = up2(acc[j][p]);
            T[(tn + j) * LDA + tm + 2 * p]     = u.x * i0;
            T[(tn + j) * LDA + tm + 2 * p + 1] = u.y * i1;
        }
    }
    __syncthreads();
#pragma unroll
    for (int i = 0; i < 8; i++) {
        int idx = tid + 256 * i;                 // 2048 float4
        int r = idx >> 5, c4 = (idx & 31) * 4;
        *(float4*)&g_oT[(size_t)(h * DD + r) * BT + b * TT + m0 + c4] =
            *(const float4*)&T[r * LDA + c4];
    }
}

// =================================================================================
// out: out = oT^T @ Wo + bo. 3-stage ring, one barrier/iter. grid (12, 64).
// =================================================================================
__global__ void __launch_bounds__(256, 2) out_gemm(const float* __restrict__ Wo,
                                                   const float* __restrict__ bo,
                                                   float* __restrict__ Out)
{
    extern __shared__ char smraw[];
    SmemG3& S = *(SmemG3*)smraw;
    const unsigned sb = s2u(smraw);
    const unsigned OFFB = (unsigned)(3 * 32 * LDA * 4);
    const int tid = threadIdx.x;
    const int n0 = blockIdx.x * 64, m0 = blockIdx.y * 128;
    const int tm = (tid >> 4) * 8, tn = (tid & 15) * 4;

    ull acc[4][4];
#pragma unroll
    for (int j = 0; j < 4; j++)
#pragma unroll
        for (int p = 0; p < 4; p++) acc[j][p] = 0ull;

    auto issue = [&](int st, int kb) {
        const float* Ab = g_oT + (size_t)kb * 32 * BT + m0;
        const float* Bb = Wo   + (size_t)kb * 32 * CC + n0;
#pragma unroll
        for (int i = 0; i < 4; i++) {
            int idx = tid + 256 * i;
            int r = idx >> 5, c = idx & 31;
            cpa16(sb + (unsigned)((st * 32 + r) * LDA + c * 4) * 4,
                  Ab + (size_t)r * BT + c * 4);
        }
#pragma unroll
        for (int i = 0; i < 2; i++) {
            int idx = tid + 256 * i;
            int r = idx >> 4, c = idx & 15;
            cpa16(sb + OFFB + (unsigned)((st * 32 + r) * LDB + c * 4) * 4,
                  Bb + (size_t)r * CC + c * 4);
        }
        CP_COMMIT();
    };

    issue(0, 0);
    issue(1, 1);

    int stC = 0, stI = 2;
    for (int kt = 0; kt < 24; kt++) {
        if (kt < 23) CP_WAIT1(); else CP_WAIT0();
        __syncthreads();
        if (kt < 22) { issue(stI, kt + 2); stI = WRAP3(stI); }
        const float (*Asb)[LDA] = S.As[stC];
        const float (*Bsb)[LDB] = S.Bs[stC];
#pragma unroll 16
        for (int kk = 0; kk < 32; kk++) KSTEP(Asb, Bsb, kk)
        stC = WRAP3(stC);
    }

    const float4 bv = *(const float4*)&bo[n0 + tn];
#pragma unroll
    for (int p = 0; p < 4; p++) {
        float2 u[4];
#pragma unroll
        for (int j = 0; j < 4; j++) u[j] = up2(acc[j][p]);
        const int mlo = m0 + tm + 2 * p;
        *(float4*)&Out[(size_t)mlo * CC + n0 + tn] =
            make_float4(u[0].x + bv.x, u[1].x + bv.y, u[2].x + bv.z, u[3].x + bv.w);
        *(float4*)&Out[(size_t)(mlo + 1) * CC + n0 + tn] =
            make_float4(u[0].y + bv.x, u[1].y + bv.y, u[2].y + bv.z, u[3].y + bv.w);
    }
}

// =================================================================================
extern "C" void kernel_launch(void* const* d_in, const int* in_sizes, int n_in,
                              void* d_out, int out_size)
{
    const float* x   = (const float*)d_in[0];
    const float* ctx = (const float*)d_in[1];
    const float* Wq  = (const float*)d_in[2];
    const float* Wk  = (const float*)d_in[3];
    const float* Wv  = (const float*)d_in[4];
    const float* Wo  = (const float*)d_in[5];
    const float* bo  = (const float*)d_in[6];
    const float* rph = (const float*)d_in[7];
    const float* rpw = (const float*)d_in[8];
    float* out = (float*)d_out;

    cudaFuncSetAttribute(qkv_gemm,    cudaFuncAttributeMaxDynamicSharedMemorySize, (int)sizeof(SmemG3));
    cudaFuncSetAttribute(out_gemm,    cudaFuncAttributeMaxDynamicSharedMemorySize, (int)sizeof(SmemG3));
    cudaFuncSetAttribute(pv_gemm,     cudaFuncAttributeMaxDynamicSharedMemorySize, (int)sizeof(SmemPV));
    cudaFuncSetAttribute(scores_gemm, cudaFuncAttributeMaxDynamicSharedMemorySize, (int)sizeof(SmemS));

    // launch order keeps qkv z=0 at launch #4 (ncu's fixed sample) for clean A/B
    transpose_in<<<dim3(256, 24, 2), dim3(32, 8)>>>(x, ctx);
    qkv_gemm<<<dim3(12, 64), 256, sizeof(SmemG3)>>>(1, Wk);
    qkv_gemm<<<dim3(12, 64), 256, sizeof(SmemG3)>>>(2, Wv);
    qkv_gemm<<<dim3(12, 64), 256, sizeof(SmemG3)>>>(0, Wq);   // <- profiled
    relbias_kernel<<<BH * TT, 64>>>(rph, rpw);
    scores_gemm<<<dim3(8, 96), 256, sizeof(SmemS)>>>();
    pv_gemm<<<dim3(8, 96), 256, sizeof(SmemPV)>>>();
    out_gemm<<<dim3(12, 64), 256, sizeof(SmemG3)>>>(Wo, bo, out);
}